// round 11
// baseline (speedup 1.0000x reference)
#include <cuda_runtime.h>
#include <cstdint>
#include <cstdio>

// Problem-size capacities (from reference setup: N=20000, E=320000)
#define NMAXN 20000
#define EMAXE 320000
#define ETOT  (NMAXN + EMAXE)

// ---------------- static device scratch (no allocations allowed) ----------------
__device__ __align__(16) float g_xl1[NMAXN * 256];
__device__ __align__(16) float g_xr1[NMAXN * 256];
__device__ __align__(16) float g_h1 [NMAXN * 256];
__device__ __align__(16) float g_xl2[NMAXN * 64];
__device__ __align__(16) float g_xr2[NMAXN * 64];
__device__ __align__(16) float g_h2 [NMAXN * 64];
__device__ int   g_deg[NMAXN + 1];
__device__ int   g_off[NMAXN + 1];
__device__ int   g_cur[NMAXN];
__device__ int   g_csrc[ETOT];
__device__ float g_sum[64];
__device__ float g_sumsq[64];

// ---------------- init: deg=1 accounts for the self-loop ----------------
__global__ void k_init(int N) {
    int i = blockIdx.x * blockDim.x + threadIdx.x;
    if (i < N) g_deg[i] = 1;
    if (i < 64) { g_sum[i] = 0.f; g_sumsq[i] = 0.f; }
}

// ---------------- CSR build (by dst), E edges only (R7-proven scalar form) ----------------
__global__ void k_count(const int* __restrict__ ei, int E) {
    int i = blockIdx.x * blockDim.x + threadIdx.x;
    if (i >= E) return;
    atomicAdd(&g_deg[__ldg(ei + E + i)], 1);
}

#define SCAN_PER ((NMAXN + 1023) / 1024)
__global__ __launch_bounds__(1024) void k_scan2(int N) {
    __shared__ int sh[1024];
    int tid = threadIdx.x;
    int base = tid * SCAN_PER;
    int vals[SCAN_PER];
    int s = 0;
    #pragma unroll
    for (int i = 0; i < SCAN_PER; i++) {
        int idx = base + i;
        int v = (idx < N) ? g_deg[idx] : 0;
        vals[i] = s;          // exclusive within chunk
        s += v;
    }
    sh[tid] = s;
    __syncthreads();
    #pragma unroll
    for (int o = 1; o < 1024; o <<= 1) {
        int t = (tid >= o) ? sh[tid - o] : 0;
        __syncthreads();
        sh[tid] += t;
        __syncthreads();
    }
    int block_excl = sh[tid] - s;
    #pragma unroll
    for (int i = 0; i < SCAN_PER; i++) {
        int idx = base + i;
        if (idx < N) {
            int o = block_excl + vals[i];
            g_off[idx] = o;
            g_csrc[o] = idx;      // self-loop occupies slot 0
            g_cur[idx] = o + 1;
        }
    }
    if (tid == 1023) g_off[N] = sh[1023];
}

__global__ void k_fill(const int* __restrict__ ei, int E) {
    int i = blockIdx.x * blockDim.x + threadIdx.x;
    if (i >= E) return;
    int src = __ldg(ei + i);
    int dst = __ldg(ei + E + i);
    int pos = atomicAdd(&g_cur[dst], 1);
    g_csrc[pos] = src;
}

// ======== tf32 tensor-core GEMM, fragment-permuted smem, vectorized frag loads ========
// C_concat[M, 2H] = A[M, K] @ concat(B0, B1)[K, 2H].
// Tile 64(M) x 128(N) x 32(K), 256 thr = 8 warps (2m x 4n).
// smem A: [mi(4)][ki(4)][lane(32)][4]  -> one LDS.128 per A fragment.
// smem B: [ni(16)][ki(4)][lane(32)][2] -> one LDS.64 per B fragment.
// tf32 conversion at stage-store; gmem->reg prefetch overlaps inner loop.
__device__ __forceinline__ float tfv(float f) {
    unsigned u;
    asm("cvt.rna.tf32.f32 %0, %1;" : "=r"(u) : "f"(f));
    return __uint_as_float(u);
}

__device__ __forceinline__ void mma_tf32(float* d, const unsigned* a, unsigned b0, unsigned b1) {
    asm volatile(
        "mma.sync.aligned.m16n8k8.row.col.f32.tf32.tf32.f32 "
        "{%0,%1,%2,%3}, {%4,%5,%6,%7}, {%8,%9}, {%0,%1,%2,%3};"
        : "+f"(d[0]), "+f"(d[1]), "+f"(d[2]), "+f"(d[3])
        : "r"(a[0]), "r"(a[1]), "r"(a[2]), "r"(a[3]), "r"(b0), "r"(b1));
}

__global__ __launch_bounds__(256) void k_mma(
    const float* __restrict__ A,
    const float* __restrict__ B0, const float* __restrict__ B1,
    float* __restrict__ C0, float* __restrict__ C1,
    int M, int K, int H)
{
    __shared__ float sA[2048];   // 4*4*32*4
    __shared__ float sB[4096];   // 16*4*32*2

    int tid = threadIdx.x;
    int lane = tid & 31, warp = tid >> 5;
    int wm = warp & 1, wn = warp >> 1;
    int m0 = blockIdx.x * 64;
    int n0g = blockIdx.y * 128;

    float acc[2][4][4];
    #pragma unroll
    for (int mt = 0; mt < 2; mt++)
        #pragma unroll
        for (int nt = 0; nt < 4; nt++)
            #pragma unroll
            for (int i = 0; i < 4; i++) acc[mt][nt][i] = 0.f;

    // ---- A loader mapping: thread -> (mi, ki, g, colpair) ----
    int a_grp = tid >> 4;                 // mi*4 + ki
    int a_g   = (tid & 15) >> 1;          // 0..7
    int a_a   = tid & 1;                  // col-pair selector (tg = 2a, 2a+1)
    int a_mi  = a_grp >> 2, a_ki = a_grp & 3;
    int ar0 = m0 + a_mi * 16 + a_g;
    int ar1 = ar0 + 8;
    int r0c = (ar0 < M) ? ar0 : (M - 1);
    int r1c = (ar1 < M) ? ar1 : (M - 1);
    int ac0 = a_ki * 8 + a_a * 2;
    const float* a_p0 = A + (size_t)r0c * K + ac0;
    const float* a_p1 = A + (size_t)r1c * K + ac0;
    float* a_st = sA + (a_grp * 32 + (tid & 15) * 2) * 4;

    // ---- B loader mapping: thread -> (ni, ki, col-pair) ----
    int b_grp = tid >> 2;                 // ni*4 + ki
    int b_ki  = b_grp & 3;
    int b_s   = tid & 3;
    int b_n0  = n0g + (b_grp >> 2) * 8 + b_s * 2;
    const float* b_base = (b_n0 < H) ? (B0 + b_n0) : (B1 + b_n0 - H);
    float* b_st = sB + tid * 16;

    float2 la[4];
    float2 lb[8];

    auto load_regs = [&](int k0) {
        la[0] = *reinterpret_cast<const float2*>(a_p0 + k0);
        la[1] = *reinterpret_cast<const float2*>(a_p0 + k0 + 4);
        la[2] = *reinterpret_cast<const float2*>(a_p1 + k0);
        la[3] = *reinterpret_cast<const float2*>(a_p1 + k0 + 4);
        #pragma unroll
        for (int kk2 = 0; kk2 < 8; kk2++)
            lb[kk2] = *reinterpret_cast<const float2*>(
                b_base + (size_t)(k0 + b_ki * 8 + kk2) * H);
    };
    auto store_stage = [&]() {
        // A: fragment order e = [(g,tg),(g+8,tg),(g,tg+4),(g+8,tg+4)]
        float4 v0, v1;
        v0.x = tfv(la[0].x); v0.y = tfv(la[2].x); v0.z = tfv(la[1].x); v0.w = tfv(la[3].x);
        v1.x = tfv(la[0].y); v1.y = tfv(la[2].y); v1.z = tfv(la[1].y); v1.w = tfv(la[3].y);
        *reinterpret_cast<float4*>(a_st)     = v0;
        *reinterpret_cast<float4*>(a_st + 4) = v1;
        // B: flat[q*2+e] = B[k = ki*8 + (q&3) + 4e][n = n0 + (q>>2)]
        float r[16];
        #pragma unroll
        for (int q = 0; q < 8; q++) {
            #pragma unroll
            for (int e = 0; e < 2; e++) {
                float2 src = lb[(q & 3) + 4 * e];
                r[q * 2 + e] = tfv((q >> 2) ? src.y : src.x);
            }
        }
        #pragma unroll
        for (int j = 0; j < 4; j++)
            *reinterpret_cast<float4*>(b_st + j * 4) =
                *reinterpret_cast<float4*>(r + j * 4);
    };

    int nIter = K >> 5;

    load_regs(0);
    store_stage();
    __syncthreads();

    for (int it = 0; it < nIter; it++) {
        bool more = (it + 1) < nIter;
        if (more) load_regs((it + 1) << 5);

        #pragma unroll
        for (int kkb = 0; kkb < 4; kkb++) {
            unsigned afr[2][4];
            #pragma unroll
            for (int mt = 0; mt < 2; mt++) {
                int mi = wm * 2 + mt;
                float4 v = *reinterpret_cast<const float4*>(
                    sA + ((mi * 4 + kkb) * 32 + lane) * 4);
                afr[mt][0] = __float_as_uint(v.x);
                afr[mt][1] = __float_as_uint(v.y);
                afr[mt][2] = __float_as_uint(v.z);
                afr[mt][3] = __float_as_uint(v.w);
            }
            #pragma unroll
            for (int nt = 0; nt < 4; nt++) {
                int ni = wn * 4 + nt;
                float2 bv = *reinterpret_cast<const float2*>(
                    sB + ((ni * 4 + kkb) * 32 + lane) * 2);
                unsigned b0 = __float_as_uint(bv.x);
                unsigned b1 = __float_as_uint(bv.y);
                mma_tf32(acc[0][nt], afr[0], b0, b1);
                mma_tf32(acc[1][nt], afr[1], b0, b1);
            }
        }

        __syncthreads();
        if (more) {
            store_stage();
            __syncthreads();
        }
    }

    // store C (layout identical to previous rounds)
    int g = lane >> 2, tg = lane & 3;
    #pragma unroll
    for (int mt = 0; mt < 2; mt++) {
        int r0 = m0 + wm * 32 + mt * 16 + g;
        #pragma unroll
        for (int nt = 0; nt < 4; nt++) {
            int col = n0g + wn * 32 + nt * 8 + tg * 2;
            float* Cp = C0;
            int c = col;
            if (col >= H) { Cp = C1; c = col - H; }
            if (r0 < M)
                *reinterpret_cast<float2*>(Cp + (size_t)r0 * H + c) =
                    make_float2(acc[mt][nt][0], acc[mt][nt][1]);
            if (r0 + 8 < M)
                *reinterpret_cast<float2*>(Cp + (size_t)(r0 + 8) * H + c) =
                    make_float2(acc[mt][nt][2], acc[mt][nt][3]);
        }
    }
}

// ---------------- vector load helper ----------------
template <int V>
__device__ __forceinline__ void loadv(float* d, const float* __restrict__ p) {
    if constexpr (V == 8) {
        float4 a = *reinterpret_cast<const float4*>(p);
        float4 b = *reinterpret_cast<const float4*>(p + 4);
        d[0] = a.x; d[1] = a.y; d[2] = a.z; d[3] = a.w;
        d[4] = b.x; d[5] = b.y; d[6] = b.z; d[7] = b.w;
    } else if constexpr (V == 2) {
        float2 a = *reinterpret_cast<const float2*>(p);
        d[0] = a.x; d[1] = a.y;
    } else {
        #pragma unroll
        for (int j = 0; j < V; j++) d[j] = p[j];
    }
}

// ---------------- GATv2 node aggregation: warp per node, online softmax ----------------
// 2-edge unrolled mainloop (R7-proven config), branchy single-edge tail.
template <int HC, int VPT, int REDW, bool ELU_ACT, bool STATS>
__global__ __launch_bounds__(256) void k_node_agg(
    const float* __restrict__ xl, const float* __restrict__ xr,
    const float* __restrict__ att, const float* __restrict__ bias,
    float* __restrict__ outp, int N)
{
    __shared__ float sh_sum[STATS ? 64 : 1];
    __shared__ float sh_sq [STATS ? 64 : 1];
    int tid = threadIdx.x;
    if (STATS) {
        if (tid < 64) { sh_sum[tid] = 0.f; sh_sq[tid] = 0.f; }
        __syncthreads();
    }

    int warp = (blockIdx.x * blockDim.x + tid) >> 5;
    int lane = tid & 31;
    bool active = warp < N;
    int c0 = lane * VPT;

    if (active) {
        int n = warp;
        float xrv[VPT], attv[VPT], acc[VPT];
        loadv<VPT>(xrv, xr + (size_t)n * HC + c0);
        loadv<VPT>(attv, att + c0);
        #pragma unroll
        for (int j = 0; j < VPT; j++) acc[j] = 0.f;

        float m = __int_as_float(0xff800000);   // -inf
        float denom = 0.f;

        int s = g_off[n], e = g_off[n + 1];
        int i = s;
        for (; i + 2 <= e; i += 2) {
            int s0 = g_csrc[i];
            int s1 = g_csrc[i + 1];
            float xlv0[VPT], xlv1[VPT];
            loadv<VPT>(xlv0, xl + (size_t)s0 * HC + c0);
            loadv<VPT>(xlv1, xl + (size_t)s1 * HC + c0);

            float sc0 = 0.f, sc1 = 0.f;
            #pragma unroll
            for (int j = 0; j < VPT; j++) {
                float t0 = xlv0[j] + xrv[j];
                float t1 = xlv1[j] + xrv[j];
                t0 = (t0 > 0.f) ? t0 : 0.2f * t0;
                t1 = (t1 > 0.f) ? t1 : 0.2f * t1;
                sc0 = fmaf(t0, attv[j], sc0);
                sc1 = fmaf(t1, attv[j], sc1);
            }
            #pragma unroll
            for (int w = 1; w < REDW; w <<= 1) {
                sc0 += __shfl_xor_sync(0xffffffffu, sc0, w);
                sc1 += __shfl_xor_sync(0xffffffffu, sc1, w);
            }

            float newm = fmaxf(m, fmaxf(sc0, sc1));
            float r  = __expf(m - newm);       // 0 on first iter (m = -inf)
            float e0 = __expf(sc0 - newm);
            float e1 = __expf(sc1 - newm);
            denom = fmaf(denom, r, e0 + e1);
            #pragma unroll
            for (int j = 0; j < VPT; j++)
                acc[j] = fmaf(acc[j], r, fmaf(e0, xlv0[j], e1 * xlv1[j]));
            m = newm;
        }
        if (i < e) {
            int src = g_csrc[i];
            float xlv[VPT];
            loadv<VPT>(xlv, xl + (size_t)src * HC + c0);
            float sc = 0.f;
            #pragma unroll
            for (int j = 0; j < VPT; j++) {
                float t = xlv[j] + xrv[j];
                t = (t > 0.f) ? t : 0.2f * t;
                sc = fmaf(t, attv[j], sc);
            }
            #pragma unroll
            for (int w = 1; w < REDW; w <<= 1)
                sc += __shfl_xor_sync(0xffffffffu, sc, w);
            if (sc > m) {
                float r = __expf(m - sc);
                denom *= r;
                #pragma unroll
                for (int j = 0; j < VPT; j++) acc[j] *= r;
                m = sc;
            }
            float ex = __expf(sc - m);
            denom += ex;
            #pragma unroll
            for (int j = 0; j < VPT; j++) acc[j] = fmaf(ex, xlv[j], acc[j]);
        }

        float inv = 1.f / (denom + 1e-16f);
        #pragma unroll
        for (int j = 0; j < VPT; j++) {
            float v = acc[j] * inv + bias[c0 + j];
            if (ELU_ACT) v = (v > 0.f) ? v : (__expf(v) - 1.f);  // ELU alpha=1
            outp[(size_t)n * HC + c0 + j] = v;
            if (STATS) {
                atomicAdd(&sh_sum[c0 + j], v);
                atomicAdd(&sh_sq [c0 + j], v * v);
            }
        }
    }

    if (STATS) {
        __syncthreads();
        if (tid < 64) {
            atomicAdd(&g_sum[tid],   sh_sum[tid]);
            atomicAdd(&g_sumsq[tid], sh_sq[tid]);
        }
    }
}

// ---------------- InstanceNorm + log_softmax epilogue (warp per node) ----------------
__global__ __launch_bounds__(256) void k_final(
    const float* __restrict__ h,
    const float* __restrict__ gamma, const float* __restrict__ beta,
    float* __restrict__ out, int N)
{
    int gw = (blockIdx.x * blockDim.x + threadIdx.x) >> 5;
    int lane = threadIdx.x & 31;
    if (gw >= N) return;
    int c0 = lane * 2;

    float2 x = *reinterpret_cast<const float2*>(h + (size_t)gw * 64 + c0);
    float invN = 1.f / (float)N;

    float mean0 = g_sum[c0] * invN;
    float var0  = g_sumsq[c0] * invN - mean0 * mean0;
    float y0 = (x.x - mean0) * rsqrtf(var0 + 1e-5f) * gamma[c0] + beta[c0];

    float mean1 = g_sum[c0 + 1] * invN;
    float var1  = g_sumsq[c0 + 1] * invN - mean1 * mean1;
    float y1 = (x.y - mean1) * rsqrtf(var1 + 1e-5f) * gamma[c0 + 1] + beta[c0 + 1];

    float2 yv = make_float2(y0, y1);
    *reinterpret_cast<float2*>(out + (size_t)gw * 64 + c0) = yv;

    float mx = fmaxf(y0, y1);
    #pragma unroll
    for (int w = 1; w < 32; w <<= 1) mx = fmaxf(mx, __shfl_xor_sync(0xffffffffu, mx, w));
    float se = __expf(y0 - mx) + __expf(y1 - mx);
    #pragma unroll
    for (int w = 1; w < 32; w <<= 1) se += __shfl_xor_sync(0xffffffffu, se, w);
    float ls = __logf(se) + mx;          // log-sum-exp

    float2 lv = make_float2(y0 - ls, y1 - ls);
    *reinterpret_cast<float2*>(out + (size_t)N * 64 + (size_t)gw * 64 + c0) = lv;
}

// ---------------- host launcher ----------------
extern "C" void kernel_launch(void* const* d_in, const int* in_sizes, int n_in,
                              void* d_out, int out_size)
{
    const float* x     = (const float*)d_in[0];
    const float* Wl1   = (const float*)d_in[1];
    const float* Wr1   = (const float*)d_in[2];
    const float* att1  = (const float*)d_in[3];
    const float* b1    = (const float*)d_in[4];
    const float* Wl2   = (const float*)d_in[5];
    const float* Wr2   = (const float*)d_in[6];
    const float* att2  = (const float*)d_in[7];
    const float* b2    = (const float*)d_in[8];
    const float* gamma = (const float*)d_in[9];
    const float* beta  = (const float*)d_in[10];
    const int*   ei    = (const int*)  d_in[11];   // [2, E] int32

    int N = in_sizes[0] / 128;
    int E = in_sizes[11] / 2;

    void *p;
    cudaGetSymbolAddress(&p, g_xl1); float* xl1 = (float*)p;
    cudaGetSymbolAddress(&p, g_xr1); float* xr1 = (float*)p;
    cudaGetSymbolAddress(&p, g_h1 ); float* h1  = (float*)p;
    cudaGetSymbolAddress(&p, g_xl2); float* xl2 = (float*)p;
    cudaGetSymbolAddress(&p, g_xr2); float* xr2 = (float*)p;
    cudaGetSymbolAddress(&p, g_h2 ); float* h2  = (float*)p;

    // CSR build (R7-proven configuration)
    k_init<<<(N + 255) / 256, 256>>>(N);
    k_count<<<(E + 255) / 256, 256>>>(ei, E);
    k_scan2<<<1, 1024>>>(N);
    k_fill<<<(E + 255) / 256, 256>>>(ei, E);

    // Layer 1: [xl1 | xr1] = x @ [Wl1 | Wr1]  (M=N, K=128, H=256, 2H=512)
    {
        dim3 grid((N + 63) / 64, 4);
        k_mma<<<grid, 256>>>(x, Wl1, Wr1, xl1, xr1, N, 128, 256);
    }
    // GATv2 layer 1 (H=8, C=32) + bias + ELU
    k_node_agg<256, 8, 4, true, false><<<(N * 32 + 255) / 256, 256>>>(xl1, xr1, att1, b1, h1, N);

    // Layer 2: [xl2 | xr2] = h1 @ [Wl2 | Wr2]  (M=N, K=256, H=64, 2H=128)
    {
        dim3 grid((N + 63) / 64, 1);
        k_mma<<<grid, 256>>>(h1, Wl2, Wr2, xl2, xr2, N, 256, 64);
    }
    // GATv2 layer 2 (H=1, C=64) + bias + fused InstanceNorm stats
    k_node_agg<64, 2, 32, false, true><<<(N * 32 + 255) / 256, 256>>>(xl2, xr2, att2, b2, h2, N);

    // InstanceNorm normalize + log_softmax
    k_final<<<(N * 32 + 255) / 256, 256>>>(h2, gamma, beta, (float*)d_out, N);
}

// round 12
// speedup vs baseline: 1.0865x; 1.0865x over previous
#include <cuda_runtime.h>
#include <cstdint>
#include <cstdio>

// Problem-size capacities (from reference setup: N=20000, E=320000)
#define NMAXN 20000
#define EMAXE 320000
#define ETOT  (NMAXN + EMAXE)

// ---------------- static device scratch (no allocations allowed) ----------------
__device__ __align__(16) float g_xl1[NMAXN * 256];
__device__ __align__(16) float g_xr1[NMAXN * 256];
__device__ __align__(16) float g_h1 [NMAXN * 256];
__device__ __align__(16) float g_xl2[NMAXN * 64];
__device__ __align__(16) float g_xr2[NMAXN * 64];
__device__ __align__(16) float g_h2 [NMAXN * 64];
__device__ __align__(16) float g_xc [NMAXN * 128];   // tf32-rounded x
__device__ __align__(16) float g_wl1c[128 * 256];    // tf32-rounded weights
__device__ __align__(16) float g_wr1c[128 * 256];
__device__ __align__(16) float g_wl2c[256 * 64];
__device__ __align__(16) float g_wr2c[256 * 64];
__device__ int   g_deg[NMAXN + 1];
__device__ int   g_off[NMAXN + 1];
__device__ int   g_cur[NMAXN];
__device__ int   g_csrc[ETOT];
__device__ float g_sum[64];
__device__ float g_sumsq[64];

__device__ __forceinline__ float tfv(float f) {
    unsigned u;
    asm("cvt.rna.tf32.f32 %0, %1;" : "=r"(u) : "f"(f));
    return __uint_as_float(u);
}

// ---------------- init: deg=1 accounts for the self-loop ----------------
__global__ void k_init(int N) {
    int i = blockIdx.x * blockDim.x + threadIdx.x;
    if (i < N) g_deg[i] = 1;
    if (i < 64) { g_sum[i] = 0.f; g_sumsq[i] = 0.f; }
}

// ---------------- prep: tf32-round x and all weights into scratch copies ----------------
// float4 grid-stride over concatenated ranges.
__global__ void k_prep(const float* __restrict__ x,
                       const float* __restrict__ Wl1, const float* __restrict__ Wr1,
                       const float* __restrict__ Wl2, const float* __restrict__ Wr2,
                       int nx) // nx = N*128/4
{
    const int W1V = 128 * 256 / 4, W2V = 256 * 64 / 4;
    int tot = nx + 2 * W1V + 2 * W2V;
    for (int v = blockIdx.x * blockDim.x + threadIdx.x; v < tot;
         v += gridDim.x * blockDim.x) {
        const float4* src;
        float4* dst;
        int idx = v;
        if (idx < nx) { src = (const float4*)x + idx; dst = (float4*)g_xc + idx; }
        else if ((idx -= nx) < W1V)  { src = (const float4*)Wl1 + idx; dst = (float4*)g_wl1c + idx; }
        else if ((idx -= W1V) < W1V) { src = (const float4*)Wr1 + idx; dst = (float4*)g_wr1c + idx; }
        else if ((idx -= W1V) < W2V) { src = (const float4*)Wl2 + idx; dst = (float4*)g_wl2c + idx; }
        else { idx -= W2V;             src = (const float4*)Wr2 + idx; dst = (float4*)g_wr2c + idx; }
        float4 a = *src;
        a.x = tfv(a.x); a.y = tfv(a.y); a.z = tfv(a.z); a.w = tfv(a.w);
        *dst = a;
    }
}

// ---------------- CSR build (by dst), E edges only (R7-proven scalar form) ----------------
__global__ void k_count(const int* __restrict__ ei, int E) {
    int i = blockIdx.x * blockDim.x + threadIdx.x;
    if (i >= E) return;
    atomicAdd(&g_deg[__ldg(ei + E + i)], 1);
}

#define SCAN_PER ((NMAXN + 1023) / 1024)
__global__ __launch_bounds__(1024) void k_scan2(int N) {
    __shared__ int sh[1024];
    int tid = threadIdx.x;
    int base = tid * SCAN_PER;
    int vals[SCAN_PER];
    int s = 0;
    #pragma unroll
    for (int i = 0; i < SCAN_PER; i++) {
        int idx = base + i;
        int v = (idx < N) ? g_deg[idx] : 0;
        vals[i] = s;          // exclusive within chunk
        s += v;
    }
    sh[tid] = s;
    __syncthreads();
    #pragma unroll
    for (int o = 1; o < 1024; o <<= 1) {
        int t = (tid >= o) ? sh[tid - o] : 0;
        __syncthreads();
        sh[tid] += t;
        __syncthreads();
    }
    int block_excl = sh[tid] - s;
    #pragma unroll
    for (int i = 0; i < SCAN_PER; i++) {
        int idx = base + i;
        if (idx < N) {
            int o = block_excl + vals[i];
            g_off[idx] = o;
            g_csrc[o] = idx;      // self-loop occupies slot 0
            g_cur[idx] = o + 1;
        }
    }
    if (tid == 1023) g_off[N] = sh[1023];
}

__global__ void k_fill(const int* __restrict__ ei, int E) {
    int i = blockIdx.x * blockDim.x + threadIdx.x;
    if (i >= E) return;
    int src = __ldg(ei + i);
    int dst = __ldg(ei + E + i);
    int pos = atomicAdd(&g_cur[dst], 1);
    g_csrc[pos] = src;
}

// ---------------- tf32 tensor-core GEMM, cp.async double-buffered ----------------
// Inputs are ALREADY tf32-rounded (k_prep / agg1 epilogue) -> no cvt in inner loop.
__device__ __forceinline__ void mma_tf32(float* d, const unsigned* a, unsigned b0, unsigned b1) {
    asm volatile(
        "mma.sync.aligned.m16n8k8.row.col.f32.tf32.tf32.f32 "
        "{%0,%1,%2,%3}, {%4,%5,%6,%7}, {%8,%9}, {%0,%1,%2,%3};"
        : "+f"(d[0]), "+f"(d[1]), "+f"(d[2]), "+f"(d[3])
        : "r"(a[0]), "r"(a[1]), "r"(a[2]), "r"(a[3]), "r"(b0), "r"(b1));
}

__device__ __forceinline__ void cp_async16(uint32_t saddr, const void* g, int srcbytes) {
    asm volatile("cp.async.cg.shared.global [%0], [%1], 16, %2;"
                 :: "r"(saddr), "l"(g), "r"(srcbytes));
}

#define AS_STRIDE 36
#define BS_STRIDE 136
#define AS_STAGE  (64 * AS_STRIDE)
#define BS_STAGE  (32 * BS_STRIDE)
#define SMEM_MMA_BYTES ((2 * AS_STAGE + 2 * BS_STAGE) * 4)

__global__ __launch_bounds__(256) void k_mma(
    const float* __restrict__ A,
    const float* __restrict__ B0, const float* __restrict__ B1,
    float* __restrict__ C0, float* __restrict__ C1,
    int M, int K, int H)
{
    extern __shared__ float smem[];
    float* sAs = smem;                       // [2][64][36]
    float* sBs = smem + 2 * AS_STAGE;        // [2][32][136]

    int tid = threadIdx.x;
    int lane = tid & 31, warp = tid >> 5;
    int wm = warp & 1, wn = warp >> 1;       // 2 x 4 warp grid
    int m0 = blockIdx.x * 64;
    int n0g = blockIdx.y * 128;              // col in concatenated [0, 2H) space
    int g = lane >> 2, tg = lane & 3;

    float acc[2][4][4];
    #pragma unroll
    for (int mt = 0; mt < 2; mt++)
        #pragma unroll
        for (int nt = 0; nt < 4; nt++)
            #pragma unroll
            for (int i = 0; i < 4; i++) acc[mt][nt][i] = 0.f;

    int ar = tid >> 2;          // 0..63
    int ac = (tid & 3) * 8;     // 0,8,16,24
    int br = tid >> 3;          // 0..31
    int bc = (tid & 7) * 16;    // 0..112

    int arow = m0 + ar;
    int apred = (arow < M) ? 16 : 0;
    if (arow >= M) arow = M - 1;
    const float* abase = A + (size_t)arow * K + ac;

    const float* bsrc[4];
    #pragma unroll
    for (int i = 0; i < 4; i++) {
        int col = n0g + bc + i * 4;
        bsrc[i] = (col < H) ? (B0 + (size_t)br * H + col)
                            : (B1 + (size_t)br * H + (col - H));
    }

    uint32_t sA0 = (uint32_t)__cvta_generic_to_shared(sAs);
    uint32_t sB0 = (uint32_t)__cvta_generic_to_shared(sBs);

    int nIter = K >> 5;

    auto load_stage = [&](int k0, int st) {
        uint32_t sa = sA0 + (st * AS_STAGE + ar * AS_STRIDE + ac) * 4;
        const float* ap = abase + k0;
        cp_async16(sa,      ap,     apred);
        cp_async16(sa + 16, ap + 4, apred);
        uint32_t sb = sB0 + (st * BS_STAGE + br * BS_STRIDE + bc) * 4;
        size_t koff = (size_t)k0 * H;
        #pragma unroll
        for (int i = 0; i < 4; i++)
            cp_async16(sb + i * 16, bsrc[i] + koff, 16);
    };

    load_stage(0, 0);
    asm volatile("cp.async.commit_group;" ::: "memory");

    for (int it = 0; it < nIter; it++) {
        int st = it & 1;
        asm volatile("cp.async.wait_group 0;" ::: "memory");
        __syncthreads();
        if (it + 1 < nIter) {
            load_stage((it + 1) << 5, st ^ 1);
            asm volatile("cp.async.commit_group;" ::: "memory");
        }

        const float* As = sAs + st * AS_STAGE;
        const float* Bs = sBs + st * BS_STAGE;

        #pragma unroll
        for (int kk = 0; kk < 32; kk += 8) {
            unsigned afr[2][4];
            #pragma unroll
            for (int mt = 0; mt < 2; mt++) {
                int row = wm * 32 + mt * 16;
                afr[mt][0] = __float_as_uint(As[(row + g    ) * AS_STRIDE + kk + tg    ]);
                afr[mt][1] = __float_as_uint(As[(row + g + 8) * AS_STRIDE + kk + tg    ]);
                afr[mt][2] = __float_as_uint(As[(row + g    ) * AS_STRIDE + kk + tg + 4]);
                afr[mt][3] = __float_as_uint(As[(row + g + 8) * AS_STRIDE + kk + tg + 4]);
            }
            #pragma unroll
            for (int nt = 0; nt < 4; nt++) {
                int ncol = wn * 32 + nt * 8;
                unsigned b0 = __float_as_uint(Bs[(kk + tg    ) * BS_STRIDE + ncol + g]);
                unsigned b1 = __float_as_uint(Bs[(kk + tg + 4) * BS_STRIDE + ncol + g]);
                #pragma unroll
                for (int mt = 0; mt < 2; mt++)
                    mma_tf32(acc[mt][nt], afr[mt], b0, b1);
            }
        }
        __syncthreads();
    }

    #pragma unroll
    for (int mt = 0; mt < 2; mt++) {
        int r0 = m0 + wm * 32 + mt * 16 + g;
        #pragma unroll
        for (int nt = 0; nt < 4; nt++) {
            int col = n0g + wn * 32 + nt * 8 + tg * 2;
            float* Cp = C0;
            int c = col;
            if (col >= H) { Cp = C1; c = col - H; }
            if (r0 < M)
                *reinterpret_cast<float2*>(Cp + (size_t)r0 * H + c) =
                    make_float2(acc[mt][nt][0], acc[mt][nt][1]);
            if (r0 + 8 < M)
                *reinterpret_cast<float2*>(Cp + (size_t)(r0 + 8) * H + c) =
                    make_float2(acc[mt][nt][2], acc[mt][nt][3]);
        }
    }
}

// ---------------- vector load helper ----------------
template <int V>
__device__ __forceinline__ void loadv(float* d, const float* __restrict__ p) {
    if constexpr (V == 8) {
        float4 a = *reinterpret_cast<const float4*>(p);
        float4 b = *reinterpret_cast<const float4*>(p + 4);
        d[0] = a.x; d[1] = a.y; d[2] = a.z; d[3] = a.w;
        d[4] = b.x; d[5] = b.y; d[6] = b.z; d[7] = b.w;
    } else if constexpr (V == 2) {
        float2 a = *reinterpret_cast<const float2*>(p);
        d[0] = a.x; d[1] = a.y;
    } else {
        #pragma unroll
        for (int j = 0; j < V; j++) d[j] = p[j];
    }
}

// ---------------- GATv2 node aggregation: warp per node, online softmax ----------------
// 2-edge unrolled mainloop (R7-proven config), branchy single-edge tail.
// TF32OUT: round the output to tf32 (it feeds the next GEMM as A; identical
// numerics to converting inside the GEMM, but free here).
template <int HC, int VPT, int REDW, bool ELU_ACT, bool STATS, bool TF32OUT>
__global__ __launch_bounds__(256) void k_node_agg(
    const float* __restrict__ xl, const float* __restrict__ xr,
    const float* __restrict__ att, const float* __restrict__ bias,
    float* __restrict__ outp, int N)
{
    __shared__ float sh_sum[STATS ? 64 : 1];
    __shared__ float sh_sq [STATS ? 64 : 1];
    int tid = threadIdx.x;
    if (STATS) {
        if (tid < 64) { sh_sum[tid] = 0.f; sh_sq[tid] = 0.f; }
        __syncthreads();
    }

    int warp = (blockIdx.x * blockDim.x + tid) >> 5;
    int lane = tid & 31;
    bool active = warp < N;
    int c0 = lane * VPT;

    if (active) {
        int n = warp;
        float xrv[VPT], attv[VPT], acc[VPT];
        loadv<VPT>(xrv, xr + (size_t)n * HC + c0);
        loadv<VPT>(attv, att + c0);
        #pragma unroll
        for (int j = 0; j < VPT; j++) acc[j] = 0.f;

        float m = __int_as_float(0xff800000);   // -inf
        float denom = 0.f;

        int s = g_off[n], e = g_off[n + 1];
        int i = s;
        for (; i + 2 <= e; i += 2) {
            int s0 = g_csrc[i];
            int s1 = g_csrc[i + 1];
            float xlv0[VPT], xlv1[VPT];
            loadv<VPT>(xlv0, xl + (size_t)s0 * HC + c0);
            loadv<VPT>(xlv1, xl + (size_t)s1 * HC + c0);

            float sc0 = 0.f, sc1 = 0.f;
            #pragma unroll
            for (int j = 0; j < VPT; j++) {
                float t0 = xlv0[j] + xrv[j];
                float t1 = xlv1[j] + xrv[j];
                t0 = (t0 > 0.f) ? t0 : 0.2f * t0;
                t1 = (t1 > 0.f) ? t1 : 0.2f * t1;
                sc0 = fmaf(t0, attv[j], sc0);
                sc1 = fmaf(t1, attv[j], sc1);
            }
            #pragma unroll
            for (int w = 1; w < REDW; w <<= 1) {
                sc0 += __shfl_xor_sync(0xffffffffu, sc0, w);
                sc1 += __shfl_xor_sync(0xffffffffu, sc1, w);
            }

            float newm = fmaxf(m, fmaxf(sc0, sc1));
            float r  = __expf(m - newm);       // 0 on first iter (m = -inf)
            float e0 = __expf(sc0 - newm);
            float e1 = __expf(sc1 - newm);
            denom = fmaf(denom, r, e0 + e1);
            #pragma unroll
            for (int j = 0; j < VPT; j++)
                acc[j] = fmaf(acc[j], r, fmaf(e0, xlv0[j], e1 * xlv1[j]));
            m = newm;
        }
        if (i < e) {
            int src = g_csrc[i];
            float xlv[VPT];
            loadv<VPT>(xlv, xl + (size_t)src * HC + c0);
            float sc = 0.f;
            #pragma unroll
            for (int j = 0; j < VPT; j++) {
                float t = xlv[j] + xrv[j];
                t = (t > 0.f) ? t : 0.2f * t;
                sc = fmaf(t, attv[j], sc);
            }
            #pragma unroll
            for (int w = 1; w < REDW; w <<= 1)
                sc += __shfl_xor_sync(0xffffffffu, sc, w);
            if (sc > m) {
                float r = __expf(m - sc);
                denom *= r;
                #pragma unroll
                for (int j = 0; j < VPT; j++) acc[j] *= r;
                m = sc;
            }
            float ex = __expf(sc - m);
            denom += ex;
            #pragma unroll
            for (int j = 0; j < VPT; j++) acc[j] = fmaf(ex, xlv[j], acc[j]);
        }

        float inv = 1.f / (denom + 1e-16f);
        #pragma unroll
        for (int j = 0; j < VPT; j++) {
            float v = acc[j] * inv + bias[c0 + j];
            if (ELU_ACT) v = (v > 0.f) ? v : (__expf(v) - 1.f);  // ELU alpha=1
            float w = TF32OUT ? tfv(v) : v;
            outp[(size_t)n * HC + c0 + j] = w;
            if (STATS) {
                atomicAdd(&sh_sum[c0 + j], v);
                atomicAdd(&sh_sq [c0 + j], v * v);
            }
        }
    }

    if (STATS) {
        __syncthreads();
        if (tid < 64) {
            atomicAdd(&g_sum[tid],   sh_sum[tid]);
            atomicAdd(&g_sumsq[tid], sh_sq[tid]);
        }
    }
}

// ---------------- InstanceNorm + log_softmax epilogue (warp per node) ----------------
__global__ __launch_bounds__(256) void k_final(
    const float* __restrict__ h,
    const float* __restrict__ gamma, const float* __restrict__ beta,
    float* __restrict__ out, int N)
{
    int gw = (blockIdx.x * blockDim.x + threadIdx.x) >> 5;
    int lane = threadIdx.x & 31;
    if (gw >= N) return;
    int c0 = lane * 2;

    float2 x = *reinterpret_cast<const float2*>(h + (size_t)gw * 64 + c0);
    float invN = 1.f / (float)N;

    float mean0 = g_sum[c0] * invN;
    float var0  = g_sumsq[c0] * invN - mean0 * mean0;
    float y0 = (x.x - mean0) * rsqrtf(var0 + 1e-5f) * gamma[c0] + beta[c0];

    float mean1 = g_sum[c0 + 1] * invN;
    float var1  = g_sumsq[c0 + 1] * invN - mean1 * mean1;
    float y1 = (x.y - mean1) * rsqrtf(var1 + 1e-5f) * gamma[c0 + 1] + beta[c0 + 1];

    float2 yv = make_float2(y0, y1);
    *reinterpret_cast<float2*>(out + (size_t)gw * 64 + c0) = yv;

    float mx = fmaxf(y0, y1);
    #pragma unroll
    for (int w = 1; w < 32; w <<= 1) mx = fmaxf(mx, __shfl_xor_sync(0xffffffffu, mx, w));
    float se = __expf(y0 - mx) + __expf(y1 - mx);
    #pragma unroll
    for (int w = 1; w < 32; w <<= 1) se += __shfl_xor_sync(0xffffffffu, se, w);
    float ls = __logf(se) + mx;          // log-sum-exp

    float2 lv = make_float2(y0 - ls, y1 - ls);
    *reinterpret_cast<float2*>(out + (size_t)N * 64 + (size_t)gw * 64 + c0) = lv;
}

// ---------------- host launcher ----------------
extern "C" void kernel_launch(void* const* d_in, const int* in_sizes, int n_in,
                              void* d_out, int out_size)
{
    const float* x     = (const float*)d_in[0];
    const float* Wl1   = (const float*)d_in[1];
    const float* Wr1   = (const float*)d_in[2];
    const float* att1  = (const float*)d_in[3];
    const float* b1    = (const float*)d_in[4];
    const float* Wl2   = (const float*)d_in[5];
    const float* Wr2   = (const float*)d_in[6];
    const float* att2  = (const float*)d_in[7];
    const float* b2    = (const float*)d_in[8];
    const float* gamma = (const float*)d_in[9];
    const float* beta  = (const float*)d_in[10];
    const int*   ei    = (const int*)  d_in[11];   // [2, E] int32

    int N = in_sizes[0] / 128;
    int E = in_sizes[11] / 2;

    void *p;
    cudaGetSymbolAddress(&p, g_xl1); float* xl1 = (float*)p;
    cudaGetSymbolAddress(&p, g_xr1); float* xr1 = (float*)p;
    cudaGetSymbolAddress(&p, g_h1 ); float* h1  = (float*)p;
    cudaGetSymbolAddress(&p, g_xl2); float* xl2 = (float*)p;
    cudaGetSymbolAddress(&p, g_xr2); float* xr2 = (float*)p;
    cudaGetSymbolAddress(&p, g_h2 ); float* h2  = (float*)p;
    cudaGetSymbolAddress(&p, g_xc  ); float* xc   = (float*)p;
    cudaGetSymbolAddress(&p, g_wl1c); float* wl1c = (float*)p;
    cudaGetSymbolAddress(&p, g_wr1c); float* wr1c = (float*)p;
    cudaGetSymbolAddress(&p, g_wl2c); float* wl2c = (float*)p;
    cudaGetSymbolAddress(&p, g_wr2c); float* wr2c = (float*)p;

    static bool attr_set = false;
    if (!attr_set) {
        cudaFuncSetAttribute(k_mma, cudaFuncAttributeMaxDynamicSharedMemorySize,
                             SMEM_MMA_BYTES);
        attr_set = true;
    }

    // CSR build (R7-proven configuration) + tf32 pre-round pass
    k_init<<<(N + 255) / 256, 256>>>(N);
    k_prep<<<1024, 256>>>(x, Wl1, Wr1, Wl2, Wr2, N * 128 / 4);
    k_count<<<(E + 255) / 256, 256>>>(ei, E);
    k_scan2<<<1, 1024>>>(N);
    k_fill<<<(E + 255) / 256, 256>>>(ei, E);

    // Layer 1: [xl1 | xr1] = xc @ [wl1c | wr1c]  (M=N, K=128, H=256, 2H=512)
    {
        dim3 grid((N + 63) / 64, 4);
        k_mma<<<grid, 256, SMEM_MMA_BYTES>>>(xc, wl1c, wr1c, xl1, xr1, N, 128, 256);
    }
    // GATv2 layer 1 (H=8, C=32) + bias + ELU, output tf32-rounded for GEMM2
    k_node_agg<256, 8, 4, true, false, true><<<(N * 32 + 255) / 256, 256>>>(
        xl1, xr1, att1, b1, h1, N);

    // Layer 2: [xl2 | xr2] = h1 @ [wl2c | wr2c]  (M=N, K=256, H=64, 2H=128)
    {
        dim3 grid((N + 63) / 64, 1);
        k_mma<<<grid, 256, SMEM_MMA_BYTES>>>(h1, wl2c, wr2c, xl2, xr2, N, 256, 64);
    }
    // GATv2 layer 2 (H=1, C=64) + bias + fused InstanceNorm stats
    k_node_agg<64, 2, 32, false, true, false><<<(N * 32 + 255) / 256, 256>>>(
        xl2, xr2, att2, b2, h2, N);

    // InstanceNorm normalize + log_softmax
    k_final<<<(N * 32 + 255) / 256, 256>>>(h2, gamma, beta, (float*)d_out, N);
}

// round 13
// speedup vs baseline: 1.3056x; 1.2017x over previous
#include <cuda_runtime.h>
#include <cstdint>
#include <cstdio>

// Problem-size capacities (from reference setup: N=20000, E=320000)
#define NMAXN 20000
#define EMAXE 320000
#define ETOT  (NMAXN + EMAXE)

// ---------------- static device scratch (no allocations allowed) ----------------
__device__ __align__(16) float g_xl1[NMAXN * 256];
__device__ __align__(16) float g_xr1[NMAXN * 256];
__device__ __align__(16) float g_h1 [NMAXN * 256];
__device__ __align__(16) float g_xl2[NMAXN * 64];
__device__ __align__(16) float g_xr2[NMAXN * 64];
__device__ __align__(16) float g_h2 [NMAXN * 64];
__device__ __align__(16) float g_xc [NMAXN * 128];   // tf32-rounded x
__device__ __align__(16) float g_wl1c[128 * 256];    // tf32-rounded weights
__device__ __align__(16) float g_wr1c[128 * 256];
__device__ __align__(16) float g_wl2c[256 * 64];
__device__ __align__(16) float g_wr2c[256 * 64];
__device__ int   g_deg[NMAXN];
__device__ int   g_off[NMAXN];
__device__ int   g_end[NMAXN];
__device__ int   g_cur[NMAXN];
__device__ int   g_csrc[ETOT];
__device__ int   g_total;
__device__ float g_sum[64];
__device__ float g_sumsq[64];

__device__ __forceinline__ float tfv(float f) {
    unsigned u;
    asm("cvt.rna.tf32.f32 %0, %1;" : "=r"(u) : "f"(f));
    return __uint_as_float(u);
}

// ---------------- init: deg=1 accounts for the self-loop ----------------
__global__ void k_init(int N) {
    int i = blockIdx.x * blockDim.x + threadIdx.x;
    if (i < N) g_deg[i] = 1;
    if (i < 64) { g_sum[i] = 0.f; g_sumsq[i] = 0.f; }
    if (i == 64) g_total = 0;
}

// ---------------- prep: tf32-round x and all weights into scratch copies ----------------
__global__ void k_prep(const float* __restrict__ x,
                       const float* __restrict__ Wl1, const float* __restrict__ Wr1,
                       const float* __restrict__ Wl2, const float* __restrict__ Wr2,
                       int nx) // nx = N*128/4
{
    const int W1V = 128 * 256 / 4, W2V = 256 * 64 / 4;
    int tot = nx + 2 * W1V + 2 * W2V;
    for (int v = blockIdx.x * blockDim.x + threadIdx.x; v < tot;
         v += gridDim.x * blockDim.x) {
        const float4* src;
        float4* dst;
        int idx = v;
        if (idx < nx) { src = (const float4*)x + idx; dst = (float4*)g_xc + idx; }
        else if ((idx -= nx) < W1V)  { src = (const float4*)Wl1 + idx; dst = (float4*)g_wl1c + idx; }
        else if ((idx -= W1V) < W1V) { src = (const float4*)Wr1 + idx; dst = (float4*)g_wr1c + idx; }
        else if ((idx -= W1V) < W2V) { src = (const float4*)Wl2 + idx; dst = (float4*)g_wl2c + idx; }
        else { idx -= W2V;             src = (const float4*)Wr2 + idx; dst = (float4*)g_wr2c + idx; }
        float4 a = *src;
        a.x = tfv(a.x); a.y = tfv(a.y); a.z = tfv(a.z); a.w = tfv(a.w);
        *dst = a;
    }
}

// ---------------- CSR build (by dst), E edges only (R7-proven scalar form) ----------------
__global__ void k_count(const int* __restrict__ ei, int E) {
    int i = blockIdx.x * blockDim.x + threadIdx.x;
    if (i >= E) return;
    atomicAdd(&g_deg[__ldg(ei + E + i)], 1);
}

// ---------------- parallel atomic-offset "scan": one launch, 79 blocks ----------------
// Segment placement is arbitrary (atomic block base); contents per node identical.
__global__ __launch_bounds__(256) void k_offsets(int N) {
    __shared__ int wtot[8];
    __shared__ int bbase;
    int i = blockIdx.x * blockDim.x + threadIdx.x;
    int lane = threadIdx.x & 31, wid = threadIdx.x >> 5;

    int deg = (i < N) ? g_deg[i] : 0;      // g_deg already includes the +1 self-loop
    int v = deg;
    #pragma unroll
    for (int o = 1; o < 32; o <<= 1) {     // warp inclusive scan
        int t = __shfl_up_sync(0xffffffffu, v, o);
        if (lane >= o) v += t;
    }
    if (lane == 31) wtot[wid] = v;
    __syncthreads();
    if (wid == 0) {
        int w = (lane < 8) ? wtot[lane] : 0;
        #pragma unroll
        for (int o = 1; o < 8; o <<= 1) {
            int t = __shfl_up_sync(0xffffffffu, w, o);
            if (lane >= o) w += t;
        }
        if (lane < 8) wtot[lane] = w;      // inclusive warp-total scan
        if (lane == 7) bbase = atomicAdd(&g_total, w);
    }
    __syncthreads();

    if (i < N) {
        int warp_excl = (wid == 0) ? 0 : wtot[wid - 1];
        int off = bbase + warp_excl + (v - deg);
        g_off[i] = off;
        g_end[i] = off + deg;
        g_csrc[off] = i;                    // self-loop occupies slot 0
        g_cur[i] = off + 1;
    }
}

__global__ void k_fill(const int* __restrict__ ei, int E) {
    int i = blockIdx.x * blockDim.x + threadIdx.x;
    if (i >= E) return;
    int src = __ldg(ei + i);
    int dst = __ldg(ei + E + i);
    int pos = atomicAdd(&g_cur[dst], 1);
    g_csrc[pos] = src;
}

// ---------------- tf32 tensor-core GEMM, cp.async double-buffered ----------------
// Inputs are ALREADY tf32-rounded (k_prep / agg1 epilogue) -> no cvt in inner loop.
__device__ __forceinline__ void mma_tf32(float* d, const unsigned* a, unsigned b0, unsigned b1) {
    asm volatile(
        "mma.sync.aligned.m16n8k8.row.col.f32.tf32.tf32.f32 "
        "{%0,%1,%2,%3}, {%4,%5,%6,%7}, {%8,%9}, {%0,%1,%2,%3};"
        : "+f"(d[0]), "+f"(d[1]), "+f"(d[2]), "+f"(d[3])
        : "r"(a[0]), "r"(a[1]), "r"(a[2]), "r"(a[3]), "r"(b0), "r"(b1));
}

__device__ __forceinline__ void cp_async16(uint32_t saddr, const void* g, int srcbytes) {
    asm volatile("cp.async.cg.shared.global [%0], [%1], 16, %2;"
                 :: "r"(saddr), "l"(g), "r"(srcbytes));
}

#define AS_STRIDE 36
#define BS_STRIDE 136
#define AS_STAGE  (64 * AS_STRIDE)
#define BS_STAGE  (32 * BS_STRIDE)
#define SMEM_MMA_BYTES ((2 * AS_STAGE + 2 * BS_STAGE) * 4)

__global__ __launch_bounds__(256) void k_mma(
    const float* __restrict__ A,
    const float* __restrict__ B0, const float* __restrict__ B1,
    float* __restrict__ C0, float* __restrict__ C1,
    int M, int K, int H)
{
    extern __shared__ float smem[];
    float* sAs = smem;                       // [2][64][36]
    float* sBs = smem + 2 * AS_STAGE;        // [2][32][136]

    int tid = threadIdx.x;
    int lane = tid & 31, warp = tid >> 5;
    int wm = warp & 1, wn = warp >> 1;       // 2 x 4 warp grid
    int m0 = blockIdx.x * 64;
    int n0g = blockIdx.y * 128;              // col in concatenated [0, 2H) space
    int g = lane >> 2, tg = lane & 3;

    float acc[2][4][4];
    #pragma unroll
    for (int mt = 0; mt < 2; mt++)
        #pragma unroll
        for (int nt = 0; nt < 4; nt++)
            #pragma unroll
            for (int i = 0; i < 4; i++) acc[mt][nt][i] = 0.f;

    int ar = tid >> 2;          // 0..63
    int ac = (tid & 3) * 8;     // 0,8,16,24
    int br = tid >> 3;          // 0..31
    int bc = (tid & 7) * 16;    // 0..112

    int arow = m0 + ar;
    int apred = (arow < M) ? 16 : 0;
    if (arow >= M) arow = M - 1;
    const float* abase = A + (size_t)arow * K + ac;

    const float* bsrc[4];
    #pragma unroll
    for (int i = 0; i < 4; i++) {
        int col = n0g + bc + i * 4;
        bsrc[i] = (col < H) ? (B0 + (size_t)br * H + col)
                            : (B1 + (size_t)br * H + (col - H));
    }

    uint32_t sA0 = (uint32_t)__cvta_generic_to_shared(sAs);
    uint32_t sB0 = (uint32_t)__cvta_generic_to_shared(sBs);

    int nIter = K >> 5;

    auto load_stage = [&](int k0, int st) {
        uint32_t sa = sA0 + (st * AS_STAGE + ar * AS_STRIDE + ac) * 4;
        const float* ap = abase + k0;
        cp_async16(sa,      ap,     apred);
        cp_async16(sa + 16, ap + 4, apred);
        uint32_t sb = sB0 + (st * BS_STAGE + br * BS_STRIDE + bc) * 4;
        size_t koff = (size_t)k0 * H;
        #pragma unroll
        for (int i = 0; i < 4; i++)
            cp_async16(sb + i * 16, bsrc[i] + koff, 16);
    };

    load_stage(0, 0);
    asm volatile("cp.async.commit_group;" ::: "memory");

    for (int it = 0; it < nIter; it++) {
        int st = it & 1;
        asm volatile("cp.async.wait_group 0;" ::: "memory");
        __syncthreads();
        if (it + 1 < nIter) {
            load_stage((it + 1) << 5, st ^ 1);
            asm volatile("cp.async.commit_group;" ::: "memory");
        }

        const float* As = sAs + st * AS_STAGE;
        const float* Bs = sBs + st * BS_STAGE;

        #pragma unroll
        for (int kk = 0; kk < 32; kk += 8) {
            unsigned afr[2][4];
            #pragma unroll
            for (int mt = 0; mt < 2; mt++) {
                int row = wm * 32 + mt * 16;
                afr[mt][0] = __float_as_uint(As[(row + g    ) * AS_STRIDE + kk + tg    ]);
                afr[mt][1] = __float_as_uint(As[(row + g + 8) * AS_STRIDE + kk + tg    ]);
                afr[mt][2] = __float_as_uint(As[(row + g    ) * AS_STRIDE + kk + tg + 4]);
                afr[mt][3] = __float_as_uint(As[(row + g + 8) * AS_STRIDE + kk + tg + 4]);
            }
            #pragma unroll
            for (int nt = 0; nt < 4; nt++) {
                int ncol = wn * 32 + nt * 8;
                unsigned b0 = __float_as_uint(Bs[(kk + tg    ) * BS_STRIDE + ncol + g]);
                unsigned b1 = __float_as_uint(Bs[(kk + tg + 4) * BS_STRIDE + ncol + g]);
                #pragma unroll
                for (int mt = 0; mt < 2; mt++)
                    mma_tf32(acc[mt][nt], afr[mt], b0, b1);
            }
        }
        __syncthreads();
    }

    #pragma unroll
    for (int mt = 0; mt < 2; mt++) {
        int r0 = m0 + wm * 32 + mt * 16 + g;
        #pragma unroll
        for (int nt = 0; nt < 4; nt++) {
            int col = n0g + wn * 32 + nt * 8 + tg * 2;
            float* Cp = C0;
            int c = col;
            if (col >= H) { Cp = C1; c = col - H; }
            if (r0 < M)
                *reinterpret_cast<float2*>(Cp + (size_t)r0 * H + c) =
                    make_float2(acc[mt][nt][0], acc[mt][nt][1]);
            if (r0 + 8 < M)
                *reinterpret_cast<float2*>(Cp + (size_t)(r0 + 8) * H + c) =
                    make_float2(acc[mt][nt][2], acc[mt][nt][3]);
        }
    }
}

// ---------------- vector load helper ----------------
template <int V>
__device__ __forceinline__ void loadv(float* d, const float* __restrict__ p) {
    if constexpr (V == 8) {
        float4 a = *reinterpret_cast<const float4*>(p);
        float4 b = *reinterpret_cast<const float4*>(p + 4);
        d[0] = a.x; d[1] = a.y; d[2] = a.z; d[3] = a.w;
        d[4] = b.x; d[5] = b.y; d[6] = b.z; d[7] = b.w;
    } else if constexpr (V == 2) {
        float2 a = *reinterpret_cast<const float2*>(p);
        d[0] = a.x; d[1] = a.y;
    } else {
        #pragma unroll
        for (int j = 0; j < V; j++) d[j] = p[j];
    }
}

// ---------------- GATv2 node aggregation: warp per node, online softmax ----------------
// 2-edge unrolled mainloop (R7-proven config), branchy single-edge tail.
// Segment bounds: [g_off[n], g_end[n]) (atomic-offset CSR).
template <int HC, int VPT, int REDW, bool ELU_ACT, bool STATS, bool TF32OUT>
__global__ __launch_bounds__(256) void k_node_agg(
    const float* __restrict__ xl, const float* __restrict__ xr,
    const float* __restrict__ att, const float* __restrict__ bias,
    float* __restrict__ outp, int N)
{
    __shared__ float sh_sum[STATS ? 64 : 1];
    __shared__ float sh_sq [STATS ? 64 : 1];
    int tid = threadIdx.x;
    if (STATS) {
        if (tid < 64) { sh_sum[tid] = 0.f; sh_sq[tid] = 0.f; }
        __syncthreads();
    }

    int warp = (blockIdx.x * blockDim.x + tid) >> 5;
    int lane = tid & 31;
    bool active = warp < N;
    int c0 = lane * VPT;

    if (active) {
        int n = warp;
        float xrv[VPT], attv[VPT], acc[VPT];
        loadv<VPT>(xrv, xr + (size_t)n * HC + c0);
        loadv<VPT>(attv, att + c0);
        #pragma unroll
        for (int j = 0; j < VPT; j++) acc[j] = 0.f;

        float m = __int_as_float(0xff800000);   // -inf
        float denom = 0.f;

        int s = g_off[n], e = g_end[n];
        int i = s;
        for (; i + 2 <= e; i += 2) {
            int s0 = g_csrc[i];
            int s1 = g_csrc[i + 1];
            float xlv0[VPT], xlv1[VPT];
            loadv<VPT>(xlv0, xl + (size_t)s0 * HC + c0);
            loadv<VPT>(xlv1, xl + (size_t)s1 * HC + c0);

            float sc0 = 0.f, sc1 = 0.f;
            #pragma unroll
            for (int j = 0; j < VPT; j++) {
                float t0 = xlv0[j] + xrv[j];
                float t1 = xlv1[j] + xrv[j];
                t0 = (t0 > 0.f) ? t0 : 0.2f * t0;
                t1 = (t1 > 0.f) ? t1 : 0.2f * t1;
                sc0 = fmaf(t0, attv[j], sc0);
                sc1 = fmaf(t1, attv[j], sc1);
            }
            #pragma unroll
            for (int w = 1; w < REDW; w <<= 1) {
                sc0 += __shfl_xor_sync(0xffffffffu, sc0, w);
                sc1 += __shfl_xor_sync(0xffffffffu, sc1, w);
            }

            float newm = fmaxf(m, fmaxf(sc0, sc1));
            float r  = __expf(m - newm);       // 0 on first iter (m = -inf)
            float e0 = __expf(sc0 - newm);
            float e1 = __expf(sc1 - newm);
            denom = fmaf(denom, r, e0 + e1);
            #pragma unroll
            for (int j = 0; j < VPT; j++)
                acc[j] = fmaf(acc[j], r, fmaf(e0, xlv0[j], e1 * xlv1[j]));
            m = newm;
        }
        if (i < e) {
            int src = g_csrc[i];
            float xlv[VPT];
            loadv<VPT>(xlv, xl + (size_t)src * HC + c0);
            float sc = 0.f;
            #pragma unroll
            for (int j = 0; j < VPT; j++) {
                float t = xlv[j] + xrv[j];
                t = (t > 0.f) ? t : 0.2f * t;
                sc = fmaf(t, attv[j], sc);
            }
            #pragma unroll
            for (int w = 1; w < REDW; w <<= 1)
                sc += __shfl_xor_sync(0xffffffffu, sc, w);
            if (sc > m) {
                float r = __expf(m - sc);
                denom *= r;
                #pragma unroll
                for (int j = 0; j < VPT; j++) acc[j] *= r;
                m = sc;
            }
            float ex = __expf(sc - m);
            denom += ex;
            #pragma unroll
            for (int j = 0; j < VPT; j++) acc[j] = fmaf(ex, xlv[j], acc[j]);
        }

        float inv = 1.f / (denom + 1e-16f);
        #pragma unroll
        for (int j = 0; j < VPT; j++) {
            float v = acc[j] * inv + bias[c0 + j];
            if (ELU_ACT) v = (v > 0.f) ? v : (__expf(v) - 1.f);  // ELU alpha=1
            float w = TF32OUT ? tfv(v) : v;
            outp[(size_t)n * HC + c0 + j] = w;
            if (STATS) {
                atomicAdd(&sh_sum[c0 + j], v);
                atomicAdd(&sh_sq [c0 + j], v * v);
            }
        }
    }

    if (STATS) {
        __syncthreads();
        if (tid < 64) {
            atomicAdd(&g_sum[tid],   sh_sum[tid]);
            atomicAdd(&g_sumsq[tid], sh_sq[tid]);
        }
    }
}

// ---------------- InstanceNorm + log_softmax epilogue (warp per node) ----------------
__global__ __launch_bounds__(256) void k_final(
    const float* __restrict__ h,
    const float* __restrict__ gamma, const float* __restrict__ beta,
    float* __restrict__ out, int N)
{
    int gw = (blockIdx.x * blockDim.x + threadIdx.x) >> 5;
    int lane = threadIdx.x & 31;
    if (gw >= N) return;
    int c0 = lane * 2;

    float2 x = *reinterpret_cast<const float2*>(h + (size_t)gw * 64 + c0);
    float invN = 1.f / (float)N;

    float mean0 = g_sum[c0] * invN;
    float var0  = g_sumsq[c0] * invN - mean0 * mean0;
    float y0 = (x.x - mean0) * rsqrtf(var0 + 1e-5f) * gamma[c0] + beta[c0];

    float mean1 = g_sum[c0 + 1] * invN;
    float var1  = g_sumsq[c0 + 1] * invN - mean1 * mean1;
    float y1 = (x.y - mean1) * rsqrtf(var1 + 1e-5f) * gamma[c0 + 1] + beta[c0 + 1];

    float2 yv = make_float2(y0, y1);
    *reinterpret_cast<float2*>(out + (size_t)gw * 64 + c0) = yv;

    float mx = fmaxf(y0, y1);
    #pragma unroll
    for (int w = 1; w < 32; w <<= 1) mx = fmaxf(mx, __shfl_xor_sync(0xffffffffu, mx, w));
    float se = __expf(y0 - mx) + __expf(y1 - mx);
    #pragma unroll
    for (int w = 1; w < 32; w <<= 1) se += __shfl_xor_sync(0xffffffffu, se, w);
    float ls = __logf(se) + mx;          // log-sum-exp

    float2 lv = make_float2(y0 - ls, y1 - ls);
    *reinterpret_cast<float2*>(out + (size_t)N * 64 + (size_t)gw * 64 + c0) = lv;
}

// ---------------- host launcher ----------------
extern "C" void kernel_launch(void* const* d_in, const int* in_sizes, int n_in,
                              void* d_out, int out_size)
{
    const float* x     = (const float*)d_in[0];
    const float* Wl1   = (const float*)d_in[1];
    const float* Wr1   = (const float*)d_in[2];
    const float* att1  = (const float*)d_in[3];
    const float* b1    = (const float*)d_in[4];
    const float* Wl2   = (const float*)d_in[5];
    const float* Wr2   = (const float*)d_in[6];
    const float* att2  = (const float*)d_in[7];
    const float* b2    = (const float*)d_in[8];
    const float* gamma = (const float*)d_in[9];
    const float* beta  = (const float*)d_in[10];
    const int*   ei    = (const int*)  d_in[11];   // [2, E] int32

    int N = in_sizes[0] / 128;
    int E = in_sizes[11] / 2;

    void *p;
    cudaGetSymbolAddress(&p, g_xl1); float* xl1 = (float*)p;
    cudaGetSymbolAddress(&p, g_xr1); float* xr1 = (float*)p;
    cudaGetSymbolAddress(&p, g_h1 ); float* h1  = (float*)p;
    cudaGetSymbolAddress(&p, g_xl2); float* xl2 = (float*)p;
    cudaGetSymbolAddress(&p, g_xr2); float* xr2 = (float*)p;
    cudaGetSymbolAddress(&p, g_h2 ); float* h2  = (float*)p;
    cudaGetSymbolAddress(&p, g_xc  ); float* xc   = (float*)p;
    cudaGetSymbolAddress(&p, g_wl1c); float* wl1c = (float*)p;
    cudaGetSymbolAddress(&p, g_wr1c); float* wr1c = (float*)p;
    cudaGetSymbolAddress(&p, g_wl2c); float* wl2c = (float*)p;
    cudaGetSymbolAddress(&p, g_wr2c); float* wr2c = (float*)p;

    static bool attr_set = false;
    if (!attr_set) {
        cudaFuncSetAttribute(k_mma, cudaFuncAttributeMaxDynamicSharedMemorySize,
                             SMEM_MMA_BYTES);
        attr_set = true;
    }

    // CSR build: count -> parallel atomic-offset scan -> fill
    k_init<<<(N + 255) / 256, 256>>>(N);
    k_prep<<<1024, 256>>>(x, Wl1, Wr1, Wl2, Wr2, N * 128 / 4);
    k_count<<<(E + 255) / 256, 256>>>(ei, E);
    k_offsets<<<(N + 255) / 256, 256>>>(N);
    k_fill<<<(E + 255) / 256, 256>>>(ei, E);

    // Layer 1: [xl1 | xr1] = xc @ [wl1c | wr1c]  (M=N, K=128, H=256, 2H=512)
    {
        dim3 grid((N + 63) / 64, 4);
        k_mma<<<grid, 256, SMEM_MMA_BYTES>>>(xc, wl1c, wr1c, xl1, xr1, N, 128, 256);
    }
    // GATv2 layer 1 (H=8, C=32) + bias + ELU, output tf32-rounded for GEMM2
    k_node_agg<256, 8, 4, true, false, true><<<(N * 32 + 255) / 256, 256>>>(
        xl1, xr1, att1, b1, h1, N);

    // Layer 2: [xl2 | xr2] = h1 @ [wl2c | wr2c]  (M=N, K=256, H=64, 2H=128)
    {
        dim3 grid((N + 63) / 64, 1);
        k_mma<<<grid, 256, SMEM_MMA_BYTES>>>(h1, wl2c, wr2c, xl2, xr2, N, 256, 64);
    }
    // GATv2 layer 2 (H=1, C=64) + bias + fused InstanceNorm stats
    k_node_agg<64, 2, 32, false, true, false><<<(N * 32 + 255) / 256, 256>>>(
        xl2, xr2, att2, b2, h2, N);

    // InstanceNorm normalize + log_softmax
    k_final<<<(N * 32 + 255) / 256, 256>>>(h2, gamma, beta, (float*)d_out, N);
}

// round 14
// speedup vs baseline: 1.3086x; 1.0023x over previous
#include <cuda_runtime.h>
#include <cstdint>
#include <cstdio>

// Problem-size capacities (from reference setup: N=20000, E=320000)
#define NMAXN 20000
#define EMAXE 320000
#define ETOT  (NMAXN + EMAXE)

// ---------------- static device scratch (no allocations allowed) ----------------
__device__ __align__(16) float g_xl1[NMAXN * 256];
__device__ __align__(16) float g_xr1[NMAXN * 256];
__device__ __align__(16) float g_h1 [NMAXN * 256];
__device__ __align__(16) float g_xl2[NMAXN * 64];
__device__ __align__(16) float g_xr2[NMAXN * 64];
__device__ __align__(16) float g_h2 [NMAXN * 64];
__device__ __align__(16) float g_xc [NMAXN * 128];   // tf32-rounded x
__device__ __align__(16) float g_wl1c[128 * 256];    // tf32-rounded weights
__device__ __align__(16) float g_wr1c[128 * 256];
__device__ __align__(16) float g_wl2c[256 * 64];
__device__ __align__(16) float g_wr2c[256 * 64];
__device__ int   g_deg[NMAXN];
__device__ int   g_off[NMAXN];
__device__ int   g_end[NMAXN];
__device__ int   g_cur[NMAXN];
__device__ int   g_csrc[ETOT];
__device__ int   g_total;
__device__ float g_sum[64];
__device__ float g_sumsq[64];

__device__ __forceinline__ float tfv(float f) {
    unsigned u;
    asm("cvt.rna.tf32.f32 %0, %1;" : "=r"(u) : "f"(f));
    return __uint_as_float(u);
}

// ---------------- merged init + tf32-round prep (one launch) ----------------
__global__ void k_init_prep(const float* __restrict__ x,
                            const float* __restrict__ Wl1, const float* __restrict__ Wr1,
                            const float* __restrict__ Wl2, const float* __restrict__ Wr2,
                            int N, int nx) // nx = N*128/4
{
    int i = blockIdx.x * blockDim.x + threadIdx.x;
    if (i < N) g_deg[i] = 1;                 // deg=1 accounts for the self-loop
    if (i < 64) { g_sum[i] = 0.f; g_sumsq[i] = 0.f; }
    if (i == 64) g_total = 0;

    const int W1V = 128 * 256 / 4, W2V = 256 * 64 / 4;
    int tot = nx + 2 * W1V + 2 * W2V;
    for (int v = i; v < tot; v += gridDim.x * blockDim.x) {
        const float4* src;
        float4* dst;
        int idx = v;
        if (idx < nx) { src = (const float4*)x + idx; dst = (float4*)g_xc + idx; }
        else if ((idx -= nx) < W1V)  { src = (const float4*)Wl1 + idx; dst = (float4*)g_wl1c + idx; }
        else if ((idx -= W1V) < W1V) { src = (const float4*)Wr1 + idx; dst = (float4*)g_wr1c + idx; }
        else if ((idx -= W1V) < W2V) { src = (const float4*)Wl2 + idx; dst = (float4*)g_wl2c + idx; }
        else { idx -= W2V;             src = (const float4*)Wr2 + idx; dst = (float4*)g_wr2c + idx; }
        float4 a = *src;
        a.x = tfv(a.x); a.y = tfv(a.y); a.z = tfv(a.z); a.w = tfv(a.w);
        *dst = a;
    }
}

// ---------------- CSR build (by dst), 4 edges/thread (MLP=4) ----------------
__global__ void k_count(const int* __restrict__ ei, int E) {
    int i0 = (blockIdx.x * blockDim.x + threadIdx.x) * 4;
    if (i0 + 4 <= E) {
        int4 d = *reinterpret_cast<const int4*>(ei + E + i0);
        atomicAdd(&g_deg[d.x], 1);
        atomicAdd(&g_deg[d.y], 1);
        atomicAdd(&g_deg[d.z], 1);
        atomicAdd(&g_deg[d.w], 1);
    } else {
        #pragma unroll
        for (int j = 0; j < 4; j++) {
            int i = i0 + j;
            if (i < E) atomicAdd(&g_deg[__ldg(ei + E + i)], 1);
        }
    }
}

// ---------------- parallel atomic-offset "scan": one launch, 79 blocks ----------------
__global__ __launch_bounds__(256) void k_offsets(int N) {
    __shared__ int wtot[8];
    __shared__ int bbase;
    int i = blockIdx.x * blockDim.x + threadIdx.x;
    int lane = threadIdx.x & 31, wid = threadIdx.x >> 5;

    int deg = (i < N) ? g_deg[i] : 0;      // includes the +1 self-loop
    int v = deg;
    #pragma unroll
    for (int o = 1; o < 32; o <<= 1) {     // warp inclusive scan
        int t = __shfl_up_sync(0xffffffffu, v, o);
        if (lane >= o) v += t;
    }
    if (lane == 31) wtot[wid] = v;
    __syncthreads();
    if (wid == 0) {
        int w = (lane < 8) ? wtot[lane] : 0;
        #pragma unroll
        for (int o = 1; o < 8; o <<= 1) {
            int t = __shfl_up_sync(0xffffffffu, w, o);
            if (lane >= o) w += t;
        }
        if (lane < 8) wtot[lane] = w;      // inclusive warp-total scan
        if (lane == 7) bbase = atomicAdd(&g_total, w);
    }
    __syncthreads();

    if (i < N) {
        int warp_excl = (wid == 0) ? 0 : wtot[wid - 1];
        int off = bbase + warp_excl + (v - deg);
        g_off[i] = off;
        g_end[i] = off + deg;
        g_csrc[off] = i;                    // self-loop occupies slot 0
        g_cur[i] = off + 1;
    }
}

__global__ void k_fill(const int* __restrict__ ei, int E) {
    int i0 = (blockIdx.x * blockDim.x + threadIdx.x) * 4;
    if (i0 + 4 <= E) {
        int4 sv = *reinterpret_cast<const int4*>(ei + i0);
        int4 dv = *reinterpret_cast<const int4*>(ei + E + i0);
        int p0 = atomicAdd(&g_cur[dv.x], 1);
        int p1 = atomicAdd(&g_cur[dv.y], 1);
        int p2 = atomicAdd(&g_cur[dv.z], 1);
        int p3 = atomicAdd(&g_cur[dv.w], 1);
        g_csrc[p0] = sv.x;
        g_csrc[p1] = sv.y;
        g_csrc[p2] = sv.z;
        g_csrc[p3] = sv.w;
    } else {
        #pragma unroll
        for (int j = 0; j < 4; j++) {
            int i = i0 + j;
            if (i < E) {
                int src = __ldg(ei + i);
                int dst = __ldg(ei + E + i);
                int pos = atomicAdd(&g_cur[dst], 1);
                g_csrc[pos] = src;
            }
        }
    }
}

// ---------------- tf32 tensor-core GEMM, cp.async double-buffered ----------------
// Inputs are ALREADY tf32-rounded -> no cvt in inner loop.
__device__ __forceinline__ void mma_tf32(float* d, const unsigned* a, unsigned b0, unsigned b1) {
    asm volatile(
        "mma.sync.aligned.m16n8k8.row.col.f32.tf32.tf32.f32 "
        "{%0,%1,%2,%3}, {%4,%5,%6,%7}, {%8,%9}, {%0,%1,%2,%3};"
        : "+f"(d[0]), "+f"(d[1]), "+f"(d[2]), "+f"(d[3])
        : "r"(a[0]), "r"(a[1]), "r"(a[2]), "r"(a[3]), "r"(b0), "r"(b1));
}

__device__ __forceinline__ void cp_async16(uint32_t saddr, const void* g, int srcbytes) {
    asm volatile("cp.async.cg.shared.global [%0], [%1], 16, %2;"
                 :: "r"(saddr), "l"(g), "r"(srcbytes));
}

#define AS_STRIDE 36
#define BS_STRIDE 136
#define AS_STAGE  (64 * AS_STRIDE)
#define BS_STAGE  (32 * BS_STRIDE)
#define SMEM_MMA_BYTES ((2 * AS_STAGE + 2 * BS_STAGE) * 4)

__global__ __launch_bounds__(256) void k_mma(
    const float* __restrict__ A,
    const float* __restrict__ B0, const float* __restrict__ B1,
    float* __restrict__ C0, float* __restrict__ C1,
    int M, int K, int H)
{
    extern __shared__ float smem[];
    float* sAs = smem;                       // [2][64][36]
    float* sBs = smem + 2 * AS_STAGE;        // [2][32][136]

    int tid = threadIdx.x;
    int lane = tid & 31, warp = tid >> 5;
    int wm = warp & 1, wn = warp >> 1;       // 2 x 4 warp grid
    int m0 = blockIdx.x * 64;
    int n0g = blockIdx.y * 128;              // col in concatenated [0, 2H) space
    int g = lane >> 2, tg = lane & 3;

    float acc[2][4][4];
    #pragma unroll
    for (int mt = 0; mt < 2; mt++)
        #pragma unroll
        for (int nt = 0; nt < 4; nt++)
            #pragma unroll
            for (int i = 0; i < 4; i++) acc[mt][nt][i] = 0.f;

    int ar = tid >> 2;          // 0..63
    int ac = (tid & 3) * 8;     // 0,8,16,24
    int br = tid >> 3;          // 0..31
    int bc = (tid & 7) * 16;    // 0..112

    int arow = m0 + ar;
    int apred = (arow < M) ? 16 : 0;
    if (arow >= M) arow = M - 1;
    const float* abase = A + (size_t)arow * K + ac;

    const float* bsrc[4];
    #pragma unroll
    for (int i = 0; i < 4; i++) {
        int col = n0g + bc + i * 4;
        bsrc[i] = (col < H) ? (B0 + (size_t)br * H + col)
                            : (B1 + (size_t)br * H + (col - H));
    }

    uint32_t sA0 = (uint32_t)__cvta_generic_to_shared(sAs);
    uint32_t sB0 = (uint32_t)__cvta_generic_to_shared(sBs);

    int nIter = K >> 5;

    auto load_stage = [&](int k0, int st) {
        uint32_t sa = sA0 + (st * AS_STAGE + ar * AS_STRIDE + ac) * 4;
        const float* ap = abase + k0;
        cp_async16(sa,      ap,     apred);
        cp_async16(sa + 16, ap + 4, apred);
        uint32_t sb = sB0 + (st * BS_STAGE + br * BS_STRIDE + bc) * 4;
        size_t koff = (size_t)k0 * H;
        #pragma unroll
        for (int i = 0; i < 4; i++)
            cp_async16(sb + i * 16, bsrc[i] + koff, 16);
    };

    load_stage(0, 0);
    asm volatile("cp.async.commit_group;" ::: "memory");

    for (int it = 0; it < nIter; it++) {
        int st = it & 1;
        asm volatile("cp.async.wait_group 0;" ::: "memory");
        __syncthreads();
        if (it + 1 < nIter) {
            load_stage((it + 1) << 5, st ^ 1);
            asm volatile("cp.async.commit_group;" ::: "memory");
        }

        const float* As = sAs + st * AS_STAGE;
        const float* Bs = sBs + st * BS_STAGE;

        #pragma unroll
        for (int kk = 0; kk < 32; kk += 8) {
            unsigned afr[2][4];
            #pragma unroll
            for (int mt = 0; mt < 2; mt++) {
                int row = wm * 32 + mt * 16;
                afr[mt][0] = __float_as_uint(As[(row + g    ) * AS_STRIDE + kk + tg    ]);
                afr[mt][1] = __float_as_uint(As[(row + g + 8) * AS_STRIDE + kk + tg    ]);
                afr[mt][2] = __float_as_uint(As[(row + g    ) * AS_STRIDE + kk + tg + 4]);
                afr[mt][3] = __float_as_uint(As[(row + g + 8) * AS_STRIDE + kk + tg + 4]);
            }
            #pragma unroll
            for (int nt = 0; nt < 4; nt++) {
                int ncol = wn * 32 + nt * 8;
                unsigned b0 = __float_as_uint(Bs[(kk + tg    ) * BS_STRIDE + ncol + g]);
                unsigned b1 = __float_as_uint(Bs[(kk + tg + 4) * BS_STRIDE + ncol + g]);
                #pragma unroll
                for (int mt = 0; mt < 2; mt++)
                    mma_tf32(acc[mt][nt], afr[mt], b0, b1);
            }
        }
        __syncthreads();
    }

    #pragma unroll
    for (int mt = 0; mt < 2; mt++) {
        int r0 = m0 + wm * 32 + mt * 16 + g;
        #pragma unroll
        for (int nt = 0; nt < 4; nt++) {
            int col = n0g + wn * 32 + nt * 8 + tg * 2;
            float* Cp = C0;
            int c = col;
            if (col >= H) { Cp = C1; c = col - H; }
            if (r0 < M)
                *reinterpret_cast<float2*>(Cp + (size_t)r0 * H + c) =
                    make_float2(acc[mt][nt][0], acc[mt][nt][1]);
            if (r0 + 8 < M)
                *reinterpret_cast<float2*>(Cp + (size_t)(r0 + 8) * H + c) =
                    make_float2(acc[mt][nt][2], acc[mt][nt][3]);
        }
    }
}

// ---------------- vector load helper ----------------
template <int V>
__device__ __forceinline__ void loadv(float* d, const float* __restrict__ p) {
    if constexpr (V == 8) {
        float4 a = *reinterpret_cast<const float4*>(p);
        float4 b = *reinterpret_cast<const float4*>(p + 4);
        d[0] = a.x; d[1] = a.y; d[2] = a.z; d[3] = a.w;
        d[4] = b.x; d[5] = b.y; d[6] = b.z; d[7] = b.w;
    } else if constexpr (V == 2) {
        float2 a = *reinterpret_cast<const float2*>(p);
        d[0] = a.x; d[1] = a.y;
    } else {
        #pragma unroll
        for (int j = 0; j < V; j++) d[j] = p[j];
    }
}

// ---------------- GATv2 node aggregation: warp per node, online softmax ----------------
// 2-edge unrolled mainloop; optional 4-edge mainloop (UN4, only for small VPT).
template <int HC, int VPT, int REDW, bool ELU_ACT, bool STATS, bool TF32OUT, bool UN4>
__global__ __launch_bounds__(256) void k_node_agg(
    const float* __restrict__ xl, const float* __restrict__ xr,
    const float* __restrict__ att, const float* __restrict__ bias,
    float* __restrict__ outp, int N)
{
    __shared__ float sh_sum[STATS ? 64 : 1];
    __shared__ float sh_sq [STATS ? 64 : 1];
    int tid = threadIdx.x;
    if (STATS) {
        if (tid < 64) { sh_sum[tid] = 0.f; sh_sq[tid] = 0.f; }
        __syncthreads();
    }

    int warp = (blockIdx.x * blockDim.x + tid) >> 5;
    int lane = tid & 31;
    bool active = warp < N;
    int c0 = lane * VPT;

    if (active) {
        int n = warp;
        float xrv[VPT], attv[VPT], acc[VPT];
        loadv<VPT>(xrv, xr + (size_t)n * HC + c0);
        loadv<VPT>(attv, att + c0);
        #pragma unroll
        for (int j = 0; j < VPT; j++) acc[j] = 0.f;

        float m = __int_as_float(0xff800000);   // -inf
        float denom = 0.f;

        int s = g_off[n], e = g_end[n];
        int i = s;

        if (UN4) {
            for (; i + 4 <= e; i += 4) {
                int s0 = g_csrc[i], s1 = g_csrc[i + 1];
                int s2 = g_csrc[i + 2], s3 = g_csrc[i + 3];
                float x0[VPT], x1[VPT], x2[VPT], x3[VPT];
                loadv<VPT>(x0, xl + (size_t)s0 * HC + c0);
                loadv<VPT>(x1, xl + (size_t)s1 * HC + c0);
                loadv<VPT>(x2, xl + (size_t)s2 * HC + c0);
                loadv<VPT>(x3, xl + (size_t)s3 * HC + c0);

                float sc0 = 0.f, sc1 = 0.f, sc2 = 0.f, sc3 = 0.f;
                #pragma unroll
                for (int j = 0; j < VPT; j++) {
                    float t0 = x0[j] + xrv[j], t1 = x1[j] + xrv[j];
                    float t2 = x2[j] + xrv[j], t3 = x3[j] + xrv[j];
                    t0 = (t0 > 0.f) ? t0 : 0.2f * t0;
                    t1 = (t1 > 0.f) ? t1 : 0.2f * t1;
                    t2 = (t2 > 0.f) ? t2 : 0.2f * t2;
                    t3 = (t3 > 0.f) ? t3 : 0.2f * t3;
                    sc0 = fmaf(t0, attv[j], sc0);
                    sc1 = fmaf(t1, attv[j], sc1);
                    sc2 = fmaf(t2, attv[j], sc2);
                    sc3 = fmaf(t3, attv[j], sc3);
                }
                #pragma unroll
                for (int w = 1; w < REDW; w <<= 1) {
                    sc0 += __shfl_xor_sync(0xffffffffu, sc0, w);
                    sc1 += __shfl_xor_sync(0xffffffffu, sc1, w);
                    sc2 += __shfl_xor_sync(0xffffffffu, sc2, w);
                    sc3 += __shfl_xor_sync(0xffffffffu, sc3, w);
                }
                float newm = fmaxf(fmaxf(m, fmaxf(sc0, sc1)), fmaxf(sc2, sc3));
                float r  = __expf(m - newm);
                float e0 = __expf(sc0 - newm);
                float e1 = __expf(sc1 - newm);
                float e2 = __expf(sc2 - newm);
                float e3 = __expf(sc3 - newm);
                denom = fmaf(denom, r, (e0 + e1) + (e2 + e3));
                #pragma unroll
                for (int j = 0; j < VPT; j++) {
                    float t = fmaf(e0, x0[j], e1 * x1[j]);
                    t = fmaf(e2, x2[j], t);
                    t = fmaf(e3, x3[j], t);
                    acc[j] = fmaf(acc[j], r, t);
                }
                m = newm;
            }
        }

        for (; i + 2 <= e; i += 2) {
            int s0 = g_csrc[i];
            int s1 = g_csrc[i + 1];
            float xlv0[VPT], xlv1[VPT];
            loadv<VPT>(xlv0, xl + (size_t)s0 * HC + c0);
            loadv<VPT>(xlv1, xl + (size_t)s1 * HC + c0);

            float sc0 = 0.f, sc1 = 0.f;
            #pragma unroll
            for (int j = 0; j < VPT; j++) {
                float t0 = xlv0[j] + xrv[j];
                float t1 = xlv1[j] + xrv[j];
                t0 = (t0 > 0.f) ? t0 : 0.2f * t0;
                t1 = (t1 > 0.f) ? t1 : 0.2f * t1;
                sc0 = fmaf(t0, attv[j], sc0);
                sc1 = fmaf(t1, attv[j], sc1);
            }
            #pragma unroll
            for (int w = 1; w < REDW; w <<= 1) {
                sc0 += __shfl_xor_sync(0xffffffffu, sc0, w);
                sc1 += __shfl_xor_sync(0xffffffffu, sc1, w);
            }

            float newm = fmaxf(m, fmaxf(sc0, sc1));
            float r  = __expf(m - newm);       // 0 on first iter (m = -inf)
            float e0 = __expf(sc0 - newm);
            float e1 = __expf(sc1 - newm);
            denom = fmaf(denom, r, e0 + e1);
            #pragma unroll
            for (int j = 0; j < VPT; j++)
                acc[j] = fmaf(acc[j], r, fmaf(e0, xlv0[j], e1 * xlv1[j]));
            m = newm;
        }
        if (i < e) {
            int src = g_csrc[i];
            float xlv[VPT];
            loadv<VPT>(xlv, xl + (size_t)src * HC + c0);
            float sc = 0.f;
            #pragma unroll
            for (int j = 0; j < VPT; j++) {
                float t = xlv[j] + xrv[j];
                t = (t > 0.f) ? t : 0.2f * t;
                sc = fmaf(t, attv[j], sc);
            }
            #pragma unroll
            for (int w = 1; w < REDW; w <<= 1)
                sc += __shfl_xor_sync(0xffffffffu, sc, w);
            if (sc > m) {
                float r = __expf(m - sc);
                denom *= r;
                #pragma unroll
                for (int j = 0; j < VPT; j++) acc[j] *= r;
                m = sc;
            }
            float ex = __expf(sc - m);
            denom += ex;
            #pragma unroll
            for (int j = 0; j < VPT; j++) acc[j] = fmaf(ex, xlv[j], acc[j]);
        }

        float inv = 1.f / (denom + 1e-16f);
        #pragma unroll
        for (int j = 0; j < VPT; j++) {
            float v = acc[j] * inv + bias[c0 + j];
            if (ELU_ACT) v = (v > 0.f) ? v : (__expf(v) - 1.f);  // ELU alpha=1
            float w = TF32OUT ? tfv(v) : v;
            outp[(size_t)n * HC + c0 + j] = w;
            if (STATS) {
                atomicAdd(&sh_sum[c0 + j], v);
                atomicAdd(&sh_sq [c0 + j], v * v);
            }
        }
    }

    if (STATS) {
        __syncthreads();
        if (tid < 64) {
            atomicAdd(&g_sum[tid],   sh_sum[tid]);
            atomicAdd(&g_sumsq[tid], sh_sq[tid]);
        }
    }
}

// ---------------- InstanceNorm + log_softmax epilogue (warp per node) ----------------
__global__ __launch_bounds__(256) void k_final(
    const float* __restrict__ h,
    const float* __restrict__ gamma, const float* __restrict__ beta,
    float* __restrict__ out, int N)
{
    int gw = (blockIdx.x * blockDim.x + threadIdx.x) >> 5;
    int lane = threadIdx.x & 31;
    if (gw >= N) return;
    int c0 = lane * 2;

    float2 x = *reinterpret_cast<const float2*>(h + (size_t)gw * 64 + c0);
    float invN = 1.f / (float)N;

    float mean0 = g_sum[c0] * invN;
    float var0  = g_sumsq[c0] * invN - mean0 * mean0;
    float y0 = (x.x - mean0) * rsqrtf(var0 + 1e-5f) * gamma[c0] + beta[c0];

    float mean1 = g_sum[c0 + 1] * invN;
    float var1  = g_sumsq[c0 + 1] * invN - mean1 * mean1;
    float y1 = (x.y - mean1) * rsqrtf(var1 + 1e-5f) * gamma[c0 + 1] + beta[c0 + 1];

    float2 yv = make_float2(y0, y1);
    *reinterpret_cast<float2*>(out + (size_t)gw * 64 + c0) = yv;

    float mx = fmaxf(y0, y1);
    #pragma unroll
    for (int w = 1; w < 32; w <<= 1) mx = fmaxf(mx, __shfl_xor_sync(0xffffffffu, mx, w));
    float se = __expf(y0 - mx) + __expf(y1 - mx);
    #pragma unroll
    for (int w = 1; w < 32; w <<= 1) se += __shfl_xor_sync(0xffffffffu, se, w);
    float ls = __logf(se) + mx;          // log-sum-exp

    float2 lv = make_float2(y0 - ls, y1 - ls);
    *reinterpret_cast<float2*>(out + (size_t)N * 64 + (size_t)gw * 64 + c0) = lv;
}

// ---------------- host launcher ----------------
extern "C" void kernel_launch(void* const* d_in, const int* in_sizes, int n_in,
                              void* d_out, int out_size)
{
    const float* x     = (const float*)d_in[0];
    const float* Wl1   = (const float*)d_in[1];
    const float* Wr1   = (const float*)d_in[2];
    const float* att1  = (const float*)d_in[3];
    const float* b1    = (const float*)d_in[4];
    const float* Wl2   = (const float*)d_in[5];
    const float* Wr2   = (const float*)d_in[6];
    const float* att2  = (const float*)d_in[7];
    const float* b2    = (const float*)d_in[8];
    const float* gamma = (const float*)d_in[9];
    const float* beta  = (const float*)d_in[10];
    const int*   ei    = (const int*)  d_in[11];   // [2, E] int32

    int N = in_sizes[0] / 128;
    int E = in_sizes[11] / 2;

    void *p;
    cudaGetSymbolAddress(&p, g_xl1); float* xl1 = (float*)p;
    cudaGetSymbolAddress(&p, g_xr1); float* xr1 = (float*)p;
    cudaGetSymbolAddress(&p, g_h1 ); float* h1  = (float*)p;
    cudaGetSymbolAddress(&p, g_xl2); float* xl2 = (float*)p;
    cudaGetSymbolAddress(&p, g_xr2); float* xr2 = (float*)p;
    cudaGetSymbolAddress(&p, g_h2 ); float* h2  = (float*)p;
    cudaGetSymbolAddress(&p, g_xc  ); float* xc   = (float*)p;
    cudaGetSymbolAddress(&p, g_wl1c); float* wl1c = (float*)p;
    cudaGetSymbolAddress(&p, g_wr1c); float* wr1c = (float*)p;
    cudaGetSymbolAddress(&p, g_wl2c); float* wl2c = (float*)p;
    cudaGetSymbolAddress(&p, g_wr2c); float* wr2c = (float*)p;

    static bool attr_set = false;
    if (!attr_set) {
        cudaFuncSetAttribute(k_mma, cudaFuncAttributeMaxDynamicSharedMemorySize,
                             SMEM_MMA_BYTES);
        attr_set = true;
    }

    int e4 = (E + 3) / 4;

    // CSR build: merged init/prep -> count -> parallel offsets -> fill
    k_init_prep<<<1024, 256>>>(x, Wl1, Wr1, Wl2, Wr2, N, N * 128 / 4);
    k_count<<<(e4 + 255) / 256, 256>>>(ei, E);
    k_offsets<<<(N + 255) / 256, 256>>>(N);
    k_fill<<<(e4 + 255) / 256, 256>>>(ei, E);

    // Layer 1: [xl1 | xr1] = xc @ [wl1c | wr1c]  (M=N, K=128, H=256, 2H=512)
    {
        dim3 grid((N + 63) / 64, 4);
        k_mma<<<grid, 256, SMEM_MMA_BYTES>>>(xc, wl1c, wr1c, xl1, xr1, N, 128, 256);
    }
    // GATv2 layer 1 (H=8, C=32) + bias + ELU, output tf32-rounded for GEMM2
    k_node_agg<256, 8, 4, true, false, true, false><<<(N * 32 + 255) / 256, 256>>>(
        xl1, xr1, att1, b1, h1, N);

    // Layer 2: [xl2 | xr2] = h1 @ [wl2c | wr2c]  (M=N, K=256, H=64, 2H=128)
    {
        dim3 grid((N + 63) / 64, 1);
        k_mma<<<grid, 256, SMEM_MMA_BYTES>>>(h1, wl2c, wr2c, xl2, xr2, N, 256, 64);
    }
    // GATv2 layer 2 (H=1, C=64) + bias + fused InstanceNorm stats, 4-edge unroll
    k_node_agg<64, 2, 32, false, true, false, true><<<(N * 32 + 255) / 256, 256>>>(
        xl2, xr2, att2, b2, h2, N);

    // InstanceNorm normalize + log_softmax
    k_final<<<(N * 32 + 255) / 256, 256>>>(h2, gamma, beta, (float*)d_out, N);
}

// round 15
// speedup vs baseline: 1.3312x; 1.0173x over previous
#include <cuda_runtime.h>
#include <cstdint>
#include <cstdio>

// Problem-size capacities (from reference setup: N=20000, E=320000)
#define NMAXN 20000
#define EMAXE 320000
#define ETOT  (NMAXN + EMAXE)

// ---------------- static device scratch (no allocations allowed) ----------------
__device__ __align__(16) float g_xl1[NMAXN * 256];
__device__ __align__(16) float g_xr1[NMAXN * 256];
__device__ __align__(16) float g_h1 [NMAXN * 256];
__device__ __align__(16) float g_xl2[NMAXN * 64];
__device__ __align__(16) float g_xr2[NMAXN * 64];
__device__ __align__(16) float g_h2 [NMAXN * 64];
__device__ __align__(16) float g_xc [NMAXN * 128];   // tf32-rounded x
__device__ __align__(16) float g_wl1c[128 * 256];    // tf32-rounded weights
__device__ __align__(16) float g_wr1c[128 * 256];
__device__ __align__(16) float g_wl2c[256 * 64];
__device__ __align__(16) float g_wr2c[256 * 64];
__device__ int   g_deg[NMAXN];
__device__ int   g_off[NMAXN];
__device__ int   g_end[NMAXN];
__device__ int   g_cur[NMAXN];
__device__ int   g_csrc[ETOT];
__device__ int   g_total;
__device__ float g_sum[64];
__device__ float g_sumsq[64];

__device__ __forceinline__ float tfv(float f) {
    unsigned u;
    asm("cvt.rna.tf32.f32 %0, %1;" : "=r"(u) : "f"(f));
    return __uint_as_float(u);
}

// ---------------- CSR-side init (stream 2) ----------------
__global__ void k_initdeg(int N) {
    int i = blockIdx.x * blockDim.x + threadIdx.x;
    if (i < N) g_deg[i] = 1;                 // deg=1 accounts for the self-loop
    if (i < 64) { g_sum[i] = 0.f; g_sumsq[i] = 0.f; }
    if (i == 64) g_total = 0;
}

// ---------------- GEMM-side prep: tf32-round x and weights (stream 0) ----------------
__global__ void k_prep(const float* __restrict__ x,
                       const float* __restrict__ Wl1, const float* __restrict__ Wr1,
                       const float* __restrict__ Wl2, const float* __restrict__ Wr2,
                       int nx) // nx = N*128/4
{
    const int W1V = 128 * 256 / 4, W2V = 256 * 64 / 4;
    int tot = nx + 2 * W1V + 2 * W2V;
    for (int v = blockIdx.x * blockDim.x + threadIdx.x; v < tot;
         v += gridDim.x * blockDim.x) {
        const float4* src;
        float4* dst;
        int idx = v;
        if (idx < nx) { src = (const float4*)x + idx; dst = (float4*)g_xc + idx; }
        else if ((idx -= nx) < W1V)  { src = (const float4*)Wl1 + idx; dst = (float4*)g_wl1c + idx; }
        else if ((idx -= W1V) < W1V) { src = (const float4*)Wr1 + idx; dst = (float4*)g_wr1c + idx; }
        else if ((idx -= W1V) < W2V) { src = (const float4*)Wl2 + idx; dst = (float4*)g_wl2c + idx; }
        else { idx -= W2V;             src = (const float4*)Wr2 + idx; dst = (float4*)g_wr2c + idx; }
        float4 a = *src;
        a.x = tfv(a.x); a.y = tfv(a.y); a.z = tfv(a.z); a.w = tfv(a.w);
        *dst = a;
    }
}

// ---------------- CSR build (by dst), 4 edges/thread ----------------
__global__ void k_count(const int* __restrict__ ei, int E) {
    int i0 = (blockIdx.x * blockDim.x + threadIdx.x) * 4;
    if (i0 + 4 <= E) {
        int4 d = *reinterpret_cast<const int4*>(ei + E + i0);
        atomicAdd(&g_deg[d.x], 1);
        atomicAdd(&g_deg[d.y], 1);
        atomicAdd(&g_deg[d.z], 1);
        atomicAdd(&g_deg[d.w], 1);
    } else {
        #pragma unroll
        for (int j = 0; j < 4; j++) {
            int i = i0 + j;
            if (i < E) atomicAdd(&g_deg[__ldg(ei + E + i)], 1);
        }
    }
}

// ---------------- parallel atomic-offset "scan": one launch, 79 blocks ----------------
__global__ __launch_bounds__(256) void k_offsets(int N) {
    __shared__ int wtot[8];
    __shared__ int bbase;
    int i = blockIdx.x * blockDim.x + threadIdx.x;
    int lane = threadIdx.x & 31, wid = threadIdx.x >> 5;

    int deg = (i < N) ? g_deg[i] : 0;      // includes the +1 self-loop
    int v = deg;
    #pragma unroll
    for (int o = 1; o < 32; o <<= 1) {     // warp inclusive scan
        int t = __shfl_up_sync(0xffffffffu, v, o);
        if (lane >= o) v += t;
    }
    if (lane == 31) wtot[wid] = v;
    __syncthreads();
    if (wid == 0) {
        int w = (lane < 8) ? wtot[lane] : 0;
        #pragma unroll
        for (int o = 1; o < 8; o <<= 1) {
            int t = __shfl_up_sync(0xffffffffu, w, o);
            if (lane >= o) w += t;
        }
        if (lane < 8) wtot[lane] = w;      // inclusive warp-total scan
        if (lane == 7) bbase = atomicAdd(&g_total, w);
    }
    __syncthreads();

    if (i < N) {
        int warp_excl = (wid == 0) ? 0 : wtot[wid - 1];
        int off = bbase + warp_excl + (v - deg);
        g_off[i] = off;
        g_end[i] = off + deg;
        g_csrc[off] = i;                    // self-loop occupies slot 0
        g_cur[i] = off + 1;
    }
}

__global__ void k_fill(const int* __restrict__ ei, int E) {
    int i0 = (blockIdx.x * blockDim.x + threadIdx.x) * 4;
    if (i0 + 4 <= E) {
        int4 sv = *reinterpret_cast<const int4*>(ei + i0);
        int4 dv = *reinterpret_cast<const int4*>(ei + E + i0);
        int p0 = atomicAdd(&g_cur[dv.x], 1);
        int p1 = atomicAdd(&g_cur[dv.y], 1);
        int p2 = atomicAdd(&g_cur[dv.z], 1);
        int p3 = atomicAdd(&g_cur[dv.w], 1);
        g_csrc[p0] = sv.x;
        g_csrc[p1] = sv.y;
        g_csrc[p2] = sv.z;
        g_csrc[p3] = sv.w;
    } else {
        #pragma unroll
        for (int j = 0; j < 4; j++) {
            int i = i0 + j;
            if (i < E) {
                int src = __ldg(ei + i);
                int dst = __ldg(ei + E + i);
                int pos = atomicAdd(&g_cur[dst], 1);
                g_csrc[pos] = src;
            }
        }
    }
}

// ---------------- tf32 tensor-core GEMM, cp.async double-buffered ----------------
// Inputs are ALREADY tf32-rounded -> no cvt in inner loop.
__device__ __forceinline__ void mma_tf32(float* d, const unsigned* a, unsigned b0, unsigned b1) {
    asm volatile(
        "mma.sync.aligned.m16n8k8.row.col.f32.tf32.tf32.f32 "
        "{%0,%1,%2,%3}, {%4,%5,%6,%7}, {%8,%9}, {%0,%1,%2,%3};"
        : "+f"(d[0]), "+f"(d[1]), "+f"(d[2]), "+f"(d[3])
        : "r"(a[0]), "r"(a[1]), "r"(a[2]), "r"(a[3]), "r"(b0), "r"(b1));
}

__device__ __forceinline__ void cp_async16(uint32_t saddr, const void* g, int srcbytes) {
    asm volatile("cp.async.cg.shared.global [%0], [%1], 16, %2;"
                 :: "r"(saddr), "l"(g), "r"(srcbytes));
}

#define AS_STRIDE 36
#define BS_STRIDE 136
#define AS_STAGE  (64 * AS_STRIDE)
#define BS_STAGE  (32 * BS_STRIDE)
#define SMEM_MMA_BYTES ((2 * AS_STAGE + 2 * BS_STAGE) * 4)

__global__ __launch_bounds__(256) void k_mma(
    const float* __restrict__ A,
    const float* __restrict__ B0, const float* __restrict__ B1,
    float* __restrict__ C0, float* __restrict__ C1,
    int M, int K, int H)
{
    extern __shared__ float smem[];
    float* sAs = smem;                       // [2][64][36]
    float* sBs = smem + 2 * AS_STAGE;        // [2][32][136]

    int tid = threadIdx.x;
    int lane = tid & 31, warp = tid >> 5;
    int wm = warp & 1, wn = warp >> 1;       // 2 x 4 warp grid
    int m0 = blockIdx.x * 64;
    int n0g = blockIdx.y * 128;              // col in concatenated [0, 2H) space
    int g = lane >> 2, tg = lane & 3;

    float acc[2][4][4];
    #pragma unroll
    for (int mt = 0; mt < 2; mt++)
        #pragma unroll
        for (int nt = 0; nt < 4; nt++)
            #pragma unroll
            for (int i = 0; i < 4; i++) acc[mt][nt][i] = 0.f;

    int ar = tid >> 2;          // 0..63
    int ac = (tid & 3) * 8;     // 0,8,16,24
    int br = tid >> 3;          // 0..31
    int bc = (tid & 7) * 16;    // 0..112

    int arow = m0 + ar;
    int apred = (arow < M) ? 16 : 0;
    if (arow >= M) arow = M - 1;
    const float* abase = A + (size_t)arow * K + ac;

    const float* bsrc[4];
    #pragma unroll
    for (int i = 0; i < 4; i++) {
        int col = n0g + bc + i * 4;
        bsrc[i] = (col < H) ? (B0 + (size_t)br * H + col)
                            : (B1 + (size_t)br * H + (col - H));
    }

    uint32_t sA0 = (uint32_t)__cvta_generic_to_shared(sAs);
    uint32_t sB0 = (uint32_t)__cvta_generic_to_shared(sBs);

    int nIter = K >> 5;

    auto load_stage = [&](int k0, int st) {
        uint32_t sa = sA0 + (st * AS_STAGE + ar * AS_STRIDE + ac) * 4;
        const float* ap = abase + k0;
        cp_async16(sa,      ap,     apred);
        cp_async16(sa + 16, ap + 4, apred);
        uint32_t sb = sB0 + (st * BS_STAGE + br * BS_STRIDE + bc) * 4;
        size_t koff = (size_t)k0 * H;
        #pragma unroll
        for (int i = 0; i < 4; i++)
            cp_async16(sb + i * 16, bsrc[i] + koff, 16);
    };

    load_stage(0, 0);
    asm volatile("cp.async.commit_group;" ::: "memory");

    for (int it = 0; it < nIter; it++) {
        int st = it & 1;
        asm volatile("cp.async.wait_group 0;" ::: "memory");
        __syncthreads();
        if (it + 1 < nIter) {
            load_stage((it + 1) << 5, st ^ 1);
            asm volatile("cp.async.commit_group;" ::: "memory");
        }

        const float* As = sAs + st * AS_STAGE;
        const float* Bs = sBs + st * BS_STAGE;

        #pragma unroll
        for (int kk = 0; kk < 32; kk += 8) {
            unsigned afr[2][4];
            #pragma unroll
            for (int mt = 0; mt < 2; mt++) {
                int row = wm * 32 + mt * 16;
                afr[mt][0] = __float_as_uint(As[(row + g    ) * AS_STRIDE + kk + tg    ]);
                afr[mt][1] = __float_as_uint(As[(row + g + 8) * AS_STRIDE + kk + tg    ]);
                afr[mt][2] = __float_as_uint(As[(row + g    ) * AS_STRIDE + kk + tg + 4]);
                afr[mt][3] = __float_as_uint(As[(row + g + 8) * AS_STRIDE + kk + tg + 4]);
            }
            #pragma unroll
            for (int nt = 0; nt < 4; nt++) {
                int ncol = wn * 32 + nt * 8;
                unsigned b0 = __float_as_uint(Bs[(kk + tg    ) * BS_STRIDE + ncol + g]);
                unsigned b1 = __float_as_uint(Bs[(kk + tg + 4) * BS_STRIDE + ncol + g]);
                #pragma unroll
                for (int mt = 0; mt < 2; mt++)
                    mma_tf32(acc[mt][nt], afr[mt], b0, b1);
            }
        }
        __syncthreads();
    }

    #pragma unroll
    for (int mt = 0; mt < 2; mt++) {
        int r0 = m0 + wm * 32 + mt * 16 + g;
        #pragma unroll
        for (int nt = 0; nt < 4; nt++) {
            int col = n0g + wn * 32 + nt * 8 + tg * 2;
            float* Cp = C0;
            int c = col;
            if (col >= H) { Cp = C1; c = col - H; }
            if (r0 < M)
                *reinterpret_cast<float2*>(Cp + (size_t)r0 * H + c) =
                    make_float2(acc[mt][nt][0], acc[mt][nt][1]);
            if (r0 + 8 < M)
                *reinterpret_cast<float2*>(Cp + (size_t)(r0 + 8) * H + c) =
                    make_float2(acc[mt][nt][2], acc[mt][nt][3]);
        }
    }
}

// ---------------- vector load helper ----------------
template <int V>
__device__ __forceinline__ void loadv(float* d, const float* __restrict__ p) {
    if constexpr (V == 8) {
        float4 a = *reinterpret_cast<const float4*>(p);
        float4 b = *reinterpret_cast<const float4*>(p + 4);
        d[0] = a.x; d[1] = a.y; d[2] = a.z; d[3] = a.w;
        d[4] = b.x; d[5] = b.y; d[6] = b.z; d[7] = b.w;
    } else if constexpr (V == 2) {
        float2 a = *reinterpret_cast<const float2*>(p);
        d[0] = a.x; d[1] = a.y;
    } else {
        #pragma unroll
        for (int j = 0; j < V; j++) d[j] = p[j];
    }
}

// ---------------- GATv2 node aggregation: warp per node, online softmax ----------------
template <int HC, int VPT, int REDW, bool ELU_ACT, bool STATS, bool TF32OUT, bool UN4>
__global__ __launch_bounds__(256) void k_node_agg(
    const float* __restrict__ xl, const float* __restrict__ xr,
    const float* __restrict__ att, const float* __restrict__ bias,
    float* __restrict__ outp, int N)
{
    __shared__ float sh_sum[STATS ? 64 : 1];
    __shared__ float sh_sq [STATS ? 64 : 1];
    int tid = threadIdx.x;
    if (STATS) {
        if (tid < 64) { sh_sum[tid] = 0.f; sh_sq[tid] = 0.f; }
        __syncthreads();
    }

    int warp = (blockIdx.x * blockDim.x + tid) >> 5;
    int lane = tid & 31;
    bool active = warp < N;
    int c0 = lane * VPT;

    if (active) {
        int n = warp;
        float xrv[VPT], attv[VPT], acc[VPT];
        loadv<VPT>(xrv, xr + (size_t)n * HC + c0);
        loadv<VPT>(attv, att + c0);
        #pragma unroll
        for (int j = 0; j < VPT; j++) acc[j] = 0.f;

        float m = __int_as_float(0xff800000);   // -inf
        float denom = 0.f;

        int s = g_off[n], e = g_end[n];
        int i = s;

        if (UN4) {
            for (; i + 4 <= e; i += 4) {
                int s0 = g_csrc[i], s1 = g_csrc[i + 1];
                int s2 = g_csrc[i + 2], s3 = g_csrc[i + 3];
                float x0[VPT], x1[VPT], x2[VPT], x3[VPT];
                loadv<VPT>(x0, xl + (size_t)s0 * HC + c0);
                loadv<VPT>(x1, xl + (size_t)s1 * HC + c0);
                loadv<VPT>(x2, xl + (size_t)s2 * HC + c0);
                loadv<VPT>(x3, xl + (size_t)s3 * HC + c0);

                float sc0 = 0.f, sc1 = 0.f, sc2 = 0.f, sc3 = 0.f;
                #pragma unroll
                for (int j = 0; j < VPT; j++) {
                    float t0 = x0[j] + xrv[j], t1 = x1[j] + xrv[j];
                    float t2 = x2[j] + xrv[j], t3 = x3[j] + xrv[j];
                    t0 = (t0 > 0.f) ? t0 : 0.2f * t0;
                    t1 = (t1 > 0.f) ? t1 : 0.2f * t1;
                    t2 = (t2 > 0.f) ? t2 : 0.2f * t2;
                    t3 = (t3 > 0.f) ? t3 : 0.2f * t3;
                    sc0 = fmaf(t0, attv[j], sc0);
                    sc1 = fmaf(t1, attv[j], sc1);
                    sc2 = fmaf(t2, attv[j], sc2);
                    sc3 = fmaf(t3, attv[j], sc3);
                }
                #pragma unroll
                for (int w = 1; w < REDW; w <<= 1) {
                    sc0 += __shfl_xor_sync(0xffffffffu, sc0, w);
                    sc1 += __shfl_xor_sync(0xffffffffu, sc1, w);
                    sc2 += __shfl_xor_sync(0xffffffffu, sc2, w);
                    sc3 += __shfl_xor_sync(0xffffffffu, sc3, w);
                }
                float newm = fmaxf(fmaxf(m, fmaxf(sc0, sc1)), fmaxf(sc2, sc3));
                float r  = __expf(m - newm);
                float e0 = __expf(sc0 - newm);
                float e1 = __expf(sc1 - newm);
                float e2 = __expf(sc2 - newm);
                float e3 = __expf(sc3 - newm);
                denom = fmaf(denom, r, (e0 + e1) + (e2 + e3));
                #pragma unroll
                for (int j = 0; j < VPT; j++) {
                    float t = fmaf(e0, x0[j], e1 * x1[j]);
                    t = fmaf(e2, x2[j], t);
                    t = fmaf(e3, x3[j], t);
                    acc[j] = fmaf(acc[j], r, t);
                }
                m = newm;
            }
        }

        for (; i + 2 <= e; i += 2) {
            int s0 = g_csrc[i];
            int s1 = g_csrc[i + 1];
            float xlv0[VPT], xlv1[VPT];
            loadv<VPT>(xlv0, xl + (size_t)s0 * HC + c0);
            loadv<VPT>(xlv1, xl + (size_t)s1 * HC + c0);

            float sc0 = 0.f, sc1 = 0.f;
            #pragma unroll
            for (int j = 0; j < VPT; j++) {
                float t0 = xlv0[j] + xrv[j];
                float t1 = xlv1[j] + xrv[j];
                t0 = (t0 > 0.f) ? t0 : 0.2f * t0;
                t1 = (t1 > 0.f) ? t1 : 0.2f * t1;
                sc0 = fmaf(t0, attv[j], sc0);
                sc1 = fmaf(t1, attv[j], sc1);
            }
            #pragma unroll
            for (int w = 1; w < REDW; w <<= 1) {
                sc0 += __shfl_xor_sync(0xffffffffu, sc0, w);
                sc1 += __shfl_xor_sync(0xffffffffu, sc1, w);
            }

            float newm = fmaxf(m, fmaxf(sc0, sc1));
            float r  = __expf(m - newm);       // 0 on first iter (m = -inf)
            float e0 = __expf(sc0 - newm);
            float e1 = __expf(sc1 - newm);
            denom = fmaf(denom, r, e0 + e1);
            #pragma unroll
            for (int j = 0; j < VPT; j++)
                acc[j] = fmaf(acc[j], r, fmaf(e0, xlv0[j], e1 * xlv1[j]));
            m = newm;
        }
        if (i < e) {
            int src = g_csrc[i];
            float xlv[VPT];
            loadv<VPT>(xlv, xl + (size_t)src * HC + c0);
            float sc = 0.f;
            #pragma unroll
            for (int j = 0; j < VPT; j++) {
                float t = xlv[j] + xrv[j];
                t = (t > 0.f) ? t : 0.2f * t;
                sc = fmaf(t, attv[j], sc);
            }
            #pragma unroll
            for (int w = 1; w < REDW; w <<= 1)
                sc += __shfl_xor_sync(0xffffffffu, sc, w);
            if (sc > m) {
                float r = __expf(m - sc);
                denom *= r;
                #pragma unroll
                for (int j = 0; j < VPT; j++) acc[j] *= r;
                m = sc;
            }
            float ex = __expf(sc - m);
            denom += ex;
            #pragma unroll
            for (int j = 0; j < VPT; j++) acc[j] = fmaf(ex, xlv[j], acc[j]);
        }

        float inv = 1.f / (denom + 1e-16f);
        #pragma unroll
        for (int j = 0; j < VPT; j++) {
            float v = acc[j] * inv + bias[c0 + j];
            if (ELU_ACT) v = (v > 0.f) ? v : (__expf(v) - 1.f);  // ELU alpha=1
            float w = TF32OUT ? tfv(v) : v;
            outp[(size_t)n * HC + c0 + j] = w;
            if (STATS) {
                atomicAdd(&sh_sum[c0 + j], v);
                atomicAdd(&sh_sq [c0 + j], v * v);
            }
        }
    }

    if (STATS) {
        __syncthreads();
        if (tid < 64) {
            atomicAdd(&g_sum[tid],   sh_sum[tid]);
            atomicAdd(&g_sumsq[tid], sh_sq[tid]);
        }
    }
}

// ---------------- InstanceNorm + log_softmax epilogue (warp per node) ----------------
__global__ __launch_bounds__(256) void k_final(
    const float* __restrict__ h,
    const float* __restrict__ gamma, const float* __restrict__ beta,
    float* __restrict__ out, int N)
{
    int gw = (blockIdx.x * blockDim.x + threadIdx.x) >> 5;
    int lane = threadIdx.x & 31;
    if (gw >= N) return;
    int c0 = lane * 2;

    float2 x = *reinterpret_cast<const float2*>(h + (size_t)gw * 64 + c0);
    float invN = 1.f / (float)N;

    float mean0 = g_sum[c0] * invN;
    float var0  = g_sumsq[c0] * invN - mean0 * mean0;
    float y0 = (x.x - mean0) * rsqrtf(var0 + 1e-5f) * gamma[c0] + beta[c0];

    float mean1 = g_sum[c0 + 1] * invN;
    float var1  = g_sumsq[c0 + 1] * invN - mean1 * mean1;
    float y1 = (x.y - mean1) * rsqrtf(var1 + 1e-5f) * gamma[c0 + 1] + beta[c0 + 1];

    float2 yv = make_float2(y0, y1);
    *reinterpret_cast<float2*>(out + (size_t)gw * 64 + c0) = yv;

    float mx = fmaxf(y0, y1);
    #pragma unroll
    for (int w = 1; w < 32; w <<= 1) mx = fmaxf(mx, __shfl_xor_sync(0xffffffffu, mx, w));
    float se = __expf(y0 - mx) + __expf(y1 - mx);
    #pragma unroll
    for (int w = 1; w < 32; w <<= 1) se += __shfl_xor_sync(0xffffffffu, se, w);
    float ls = __logf(se) + mx;          // log-sum-exp

    float2 lv = make_float2(y0 - ls, y1 - ls);
    *reinterpret_cast<float2*>(out + (size_t)N * 64 + (size_t)gw * 64 + c0) = lv;
}

// ---------------- host launcher ----------------
extern "C" void kernel_launch(void* const* d_in, const int* in_sizes, int n_in,
                              void* d_out, int out_size)
{
    const float* x     = (const float*)d_in[0];
    const float* Wl1   = (const float*)d_in[1];
    const float* Wr1   = (const float*)d_in[2];
    const float* att1  = (const float*)d_in[3];
    const float* b1    = (const float*)d_in[4];
    const float* Wl2   = (const float*)d_in[5];
    const float* Wr2   = (const float*)d_in[6];
    const float* att2  = (const float*)d_in[7];
    const float* b2    = (const float*)d_in[8];
    const float* gamma = (const float*)d_in[9];
    const float* beta  = (const float*)d_in[10];
    const int*   ei    = (const int*)  d_in[11];   // [2, E] int32

    int N = in_sizes[0] / 128;
    int E = in_sizes[11] / 2;

    void *p;
    cudaGetSymbolAddress(&p, g_xl1); float* xl1 = (float*)p;
    cudaGetSymbolAddress(&p, g_xr1); float* xr1 = (float*)p;
    cudaGetSymbolAddress(&p, g_h1 ); float* h1  = (float*)p;
    cudaGetSymbolAddress(&p, g_xl2); float* xl2 = (float*)p;
    cudaGetSymbolAddress(&p, g_xr2); float* xr2 = (float*)p;
    cudaGetSymbolAddress(&p, g_h2 ); float* h2  = (float*)p;
    cudaGetSymbolAddress(&p, g_xc  ); float* xc   = (float*)p;
    cudaGetSymbolAddress(&p, g_wl1c); float* wl1c = (float*)p;
    cudaGetSymbolAddress(&p, g_wr1c); float* wr1c = (float*)p;
    cudaGetSymbolAddress(&p, g_wl2c); float* wl2c = (float*)p;
    cudaGetSymbolAddress(&p, g_wr2c); float* wr2c = (float*)p;

    static cudaStream_t s2 = nullptr;
    static cudaEvent_t evFork = nullptr, evJoin = nullptr;
    static bool init_done = false;
    if (!init_done) {
        cudaFuncSetAttribute(k_mma, cudaFuncAttributeMaxDynamicSharedMemorySize,
                             SMEM_MMA_BYTES);
        cudaStreamCreateWithFlags(&s2, cudaStreamNonBlocking);
        cudaEventCreateWithFlags(&evFork, cudaEventDisableTiming);
        cudaEventCreateWithFlags(&evJoin, cudaEventDisableTiming);
        init_done = true;
    }

    int e4 = (E + 3) / 4;

    // ---- fork: CSR build on s2, tf32 prep + GEMM1 on the main stream ----
    cudaEventRecord(evFork, 0);
    cudaStreamWaitEvent(s2, evFork, 0);

    k_initdeg<<<(N + 255) / 256, 256, 0, s2>>>(N);
    k_count<<<(e4 + 255) / 256, 256, 0, s2>>>(ei, E);
    k_offsets<<<(N + 255) / 256, 256, 0, s2>>>(N);
    k_fill<<<(e4 + 255) / 256, 256, 0, s2>>>(ei, E);
    cudaEventRecord(evJoin, s2);

    k_prep<<<1024, 256>>>(x, Wl1, Wr1, Wl2, Wr2, N * 128 / 4);
    {
        dim3 grid((N + 63) / 64, 4);
        k_mma<<<grid, 256, SMEM_MMA_BYTES>>>(xc, wl1c, wr1c, xl1, xr1, N, 128, 256);
    }

    // ---- join: everything after needs both CSR and GEMM1 ----
    cudaStreamWaitEvent(0, evJoin, 0);

    // GATv2 layer 1 (H=8, C=32) + bias + ELU, output tf32-rounded for GEMM2
    k_node_agg<256, 8, 4, true, false, true, false><<<(N * 32 + 255) / 256, 256>>>(
        xl1, xr1, att1, b1, h1, N);

    // Layer 2: [xl2 | xr2] = h1 @ [wl2c | wr2c]  (M=N, K=256, H=64, 2H=128)
    {
        dim3 grid((N + 63) / 64, 1);
        k_mma<<<grid, 256, SMEM_MMA_BYTES>>>(h1, wl2c, wr2c, xl2, xr2, N, 256, 64);
    }
    // GATv2 layer 2 (H=1, C=64) + bias + fused InstanceNorm stats, 4-edge unroll
    k_node_agg<64, 2, 32, false, true, false, true><<<(N * 32 + 255) / 256, 256>>>(
        xl2, xr2, att2, b2, h2, N);

    // InstanceNorm normalize + log_softmax
    k_final<<<(N * 32 + 255) / 256, 256>>>(h2, gamma, beta, (float*)d_out, N);
}

// round 16
// speedup vs baseline: 1.4163x; 1.0639x over previous
#include <cuda_runtime.h>
#include <cstdint>
#include <cstdio>

// Problem-size capacities (from reference setup: N=20000, E=320000)
#define NMAXN 20000
#define EMAXE 320000
#define ETOT  (NMAXN + EMAXE)
#define NMT   ((NMAXN + 63) / 64)      // 64-row M tiles

// ---------------- static device scratch (no allocations allowed) ----------------
__device__ __align__(16) float g_xl1[NMAXN * 256];
__device__ __align__(16) float g_xr1[NMAXN * 256];
__device__ __align__(16) float g_h1 [NMAXN * 256];
__device__ __align__(16) float g_xl2[NMAXN * 64];
__device__ __align__(16) float g_xr2[NMAXN * 64];
__device__ __align__(16) float g_h2 [NMAXN * 64];
__device__ __align__(16) float g_xp [NMT * 4 * 2048];   // x, tf32, fragment-permuted tiles
__device__ __align__(16) float g_w1p[4 * 4 * 4096];     // [Wl1|Wr1], tf32, fragment-permuted
__device__ __align__(16) float g_wl2c[256 * 64];        // tf32-rounded (plain) for GEMM2
__device__ __align__(16) float g_wr2c[256 * 64];
__device__ int   g_deg[NMAXN];
__device__ int   g_off[NMAXN];
__device__ int   g_end[NMAXN];
__device__ int   g_cur[NMAXN];
__device__ int   g_csrc[ETOT];
__device__ int   g_total;
__device__ float g_sum[64];
__device__ float g_sumsq[64];

__device__ __forceinline__ float tfv(float f) {
    unsigned u;
    asm("cvt.rna.tf32.f32 %0, %1;" : "=r"(u) : "f"(f));
    return __uint_as_float(u);
}

// ---------------- CSR-side init (stream 2) ----------------
__global__ void k_initdeg(int N) {
    int i = blockIdx.x * blockDim.x + threadIdx.x;
    if (i < N) g_deg[i] = 1;                 // deg=1 accounts for the self-loop
    if (i < 64) { g_sum[i] = 0.f; g_sumsq[i] = 0.f; }
    if (i == 64) g_total = 0;
}

// ---------------- prep: tf32-round + fragment-permute x and W1; plain-round W2 ----------------
// A perm: tile (64m x 32k), offset = ((mi*4+kb)*32 + g*4+tg)*4 + (r8 + 2*half)
// B perm: tile (128n x 32k), offset = ((ni*4+kb)*32 + g*4+tg)*2 + half
__global__ void k_prep(const float* __restrict__ x,
                       const float* __restrict__ Wl1, const float* __restrict__ Wr1,
                       const float* __restrict__ Wl2, const float* __restrict__ Wr2,
                       int N)
{
    int nA = N * 32;                  // (m, k4) groups over x [N,128]
    const int nB = 128 * 128;         // (k, c4) groups over concat W1 [128, 512]
    const int nW2 = 2 * 256 * 64 / 4; // float4 copy of W2
    int tot = nA + nB + nW2;
    for (int v = blockIdx.x * blockDim.x + threadIdx.x; v < tot;
         v += gridDim.x * blockDim.x) {
        if (v < nA) {
            int m = v >> 5, k0 = (v & 31) * 4;
            float4 a = *reinterpret_cast<const float4*>(x + (size_t)m * 128 + k0);
            int r = m & 63, mi = r >> 4, rr = r & 15, g = rr & 7, r8 = rr >> 3;
            int kk = k0 & 31, kb = kk >> 3, half = (kk & 7) >> 2;
            float* dst = g_xp + ((size_t)((m >> 6) * 4 + (k0 >> 5))) * 2048
                       + ((mi * 4 + kb) * 32 + g * 4) * 4 + (r8 + 2 * half);
            dst[0]  = tfv(a.x);
            dst[4]  = tfv(a.y);
            dst[8]  = tfv(a.z);
            dst[12] = tfv(a.w);
        } else if (v - nA < nB) {
            int v2 = v - nA;
            int k = v2 >> 7, c = (v2 & 127) * 4;
            const float* wsrc = (c < 256) ? (Wl1 + (size_t)k * 256 + c)
                                          : (Wr1 + (size_t)k * 256 + (c - 256));
            float4 b = *reinterpret_cast<const float4*>(wsrc);
            int ntile = c >> 7, nl = c & 127;
            int kk = k & 31, kb = kk >> 3, k8 = kk & 7, tg = k8 & 3, half = k8 >> 2;
            int ni = nl >> 3, g = nl & 7;           // g in {0,4}
            float* dst = g_w1p + (size_t)((ntile * 4 + (k >> 5))) * 4096
                       + ((ni * 4 + kb) * 32 + g * 4 + tg) * 2 + half;
            dst[0]  = tfv(b.x);
            dst[8]  = tfv(b.y);
            dst[16] = tfv(b.z);
            dst[24] = tfv(b.w);
        } else {
            int idx = v - nA - nB;
            const int W2V = 256 * 64 / 4;
            const float4* src;
            float4* dst;
            if (idx < W2V) { src = (const float4*)Wl2 + idx; dst = (float4*)g_wl2c + idx; }
            else { idx -= W2V; src = (const float4*)Wr2 + idx; dst = (float4*)g_wr2c + idx; }
            float4 a = *src;
            a.x = tfv(a.x); a.y = tfv(a.y); a.z = tfv(a.z); a.w = tfv(a.w);
            *dst = a;
        }
    }
}

// ---------------- CSR build (by dst), 4 edges/thread ----------------
__global__ void k_count(const int* __restrict__ ei, int E) {
    int i0 = (blockIdx.x * blockDim.x + threadIdx.x) * 4;
    if (i0 + 4 <= E) {
        int4 d = *reinterpret_cast<const int4*>(ei + E + i0);
        atomicAdd(&g_deg[d.x], 1);
        atomicAdd(&g_deg[d.y], 1);
        atomicAdd(&g_deg[d.z], 1);
        atomicAdd(&g_deg[d.w], 1);
    } else {
        #pragma unroll
        for (int j = 0; j < 4; j++) {
            int i = i0 + j;
            if (i < E) atomicAdd(&g_deg[__ldg(ei + E + i)], 1);
        }
    }
}

// ---------------- parallel atomic-offset "scan" ----------------
__global__ __launch_bounds__(256) void k_offsets(int N) {
    __shared__ int wtot[8];
    __shared__ int bbase;
    int i = blockIdx.x * blockDim.x + threadIdx.x;
    int lane = threadIdx.x & 31, wid = threadIdx.x >> 5;

    int deg = (i < N) ? g_deg[i] : 0;      // includes the +1 self-loop
    int v = deg;
    #pragma unroll
    for (int o = 1; o < 32; o <<= 1) {
        int t = __shfl_up_sync(0xffffffffu, v, o);
        if (lane >= o) v += t;
    }
    if (lane == 31) wtot[wid] = v;
    __syncthreads();
    if (wid == 0) {
        int w = (lane < 8) ? wtot[lane] : 0;
        #pragma unroll
        for (int o = 1; o < 8; o <<= 1) {
            int t = __shfl_up_sync(0xffffffffu, w, o);
            if (lane >= o) w += t;
        }
        if (lane < 8) wtot[lane] = w;
        if (lane == 7) bbase = atomicAdd(&g_total, w);
    }
    __syncthreads();

    if (i < N) {
        int warp_excl = (wid == 0) ? 0 : wtot[wid - 1];
        int off = bbase + warp_excl + (v - deg);
        g_off[i] = off;
        g_end[i] = off + deg;
        g_csrc[off] = i;                    // self-loop occupies slot 0
        g_cur[i] = off + 1;
    }
}

__global__ void k_fill(const int* __restrict__ ei, int E) {
    int i0 = (blockIdx.x * blockDim.x + threadIdx.x) * 4;
    if (i0 + 4 <= E) {
        int4 sv = *reinterpret_cast<const int4*>(ei + i0);
        int4 dv = *reinterpret_cast<const int4*>(ei + E + i0);
        int p0 = atomicAdd(&g_cur[dv.x], 1);
        int p1 = atomicAdd(&g_cur[dv.y], 1);
        int p2 = atomicAdd(&g_cur[dv.z], 1);
        int p3 = atomicAdd(&g_cur[dv.w], 1);
        g_csrc[p0] = sv.x;
        g_csrc[p1] = sv.y;
        g_csrc[p2] = sv.z;
        g_csrc[p3] = sv.w;
    } else {
        #pragma unroll
        for (int j = 0; j < 4; j++) {
            int i = i0 + j;
            if (i < E) {
                int src = __ldg(ei + i);
                int dst = __ldg(ei + E + i);
                int pos = atomicAdd(&g_cur[dst], 1);
                g_csrc[pos] = src;
            }
        }
    }
}

// ---------------- mma helpers ----------------
__device__ __forceinline__ void mma_tf32(float* d, const unsigned* a, unsigned b0, unsigned b1) {
    asm volatile(
        "mma.sync.aligned.m16n8k8.row.col.f32.tf32.tf32.f32 "
        "{%0,%1,%2,%3}, {%4,%5,%6,%7}, {%8,%9}, {%0,%1,%2,%3};"
        : "+f"(d[0]), "+f"(d[1]), "+f"(d[2]), "+f"(d[3])
        : "r"(a[0]), "r"(a[1]), "r"(a[2]), "r"(a[3]), "r"(b0), "r"(b1));
}

__device__ __forceinline__ void cp_async16(uint32_t saddr, const void* g, int srcbytes) {
    asm volatile("cp.async.cg.shared.global [%0], [%1], 16, %2;"
                 :: "r"(saddr), "l"(g), "r"(srcbytes));
}

// ======== GEMM1: fragment-permuted operands, 64x128 tile, K=128, H=256 ========
#define P1_AS 2048
#define P1_BS 4096
#define SMEM_P1 (2 * (P1_AS + P1_BS) * 4)

__global__ __launch_bounds__(256) void k_mma_p1(
    const float* __restrict__ Ap, const float* __restrict__ Bp,
    float* __restrict__ C0, float* __restrict__ C1, int M)
{
    const int H = 256;
    extern __shared__ float smem[];
    float* sA = smem;                 // [2][2048]
    float* sB = smem + 2 * P1_AS;     // [2][4096]

    int tid = threadIdx.x;
    int lane = tid & 31, warp = tid >> 5;
    int wm = warp & 1, wn = warp >> 1;
    const float* Abase = Ap + (size_t)blockIdx.x * 4 * P1_AS;
    const float* Bbase = Bp + (size_t)blockIdx.y * 4 * P1_BS;

    float acc[2][4][4];
    #pragma unroll
    for (int mt = 0; mt < 2; mt++)
        #pragma unroll
        for (int nt = 0; nt < 4; nt++)
            #pragma unroll
            for (int i = 0; i < 4; i++) acc[mt][nt][i] = 0.f;

    uint32_t sAu = (uint32_t)__cvta_generic_to_shared(sA);
    uint32_t sBu = (uint32_t)__cvta_generic_to_shared(sB);

    auto load = [&](int kt, int st) {
        uint32_t da = sAu + (st * P1_AS + tid * 8) * 4;
        const float* pa = Abase + kt * P1_AS + tid * 8;
        cp_async16(da,      pa,     16);
        cp_async16(da + 16, pa + 4, 16);
        uint32_t db = sBu + (st * P1_BS + tid * 16) * 4;
        const float* pb = Bbase + kt * P1_BS + tid * 16;
        cp_async16(db,      pb,      16);
        cp_async16(db + 16, pb + 4,  16);
        cp_async16(db + 32, pb + 8,  16);
        cp_async16(db + 48, pb + 12, 16);
    };

    load(0, 0);
    asm volatile("cp.async.commit_group;" ::: "memory");

    #pragma unroll
    for (int kt = 0; kt < 4; kt++) {
        int st = kt & 1;
        asm volatile("cp.async.wait_group 0;" ::: "memory");
        __syncthreads();
        if (kt < 3) {
            load(kt + 1, st ^ 1);
            asm volatile("cp.async.commit_group;" ::: "memory");
        }
        const float* As = sA + st * P1_AS;
        const float* Bs = sB + st * P1_BS;

        #pragma unroll
        for (int kb = 0; kb < 4; kb++) {
            unsigned afr[2][4];
            #pragma unroll
            for (int mt = 0; mt < 2; mt++) {
                int mi = wm * 2 + mt;
                float4 v = *reinterpret_cast<const float4*>(
                    As + ((mi * 4 + kb) * 32 + lane) * 4);
                afr[mt][0] = __float_as_uint(v.x);
                afr[mt][1] = __float_as_uint(v.y);
                afr[mt][2] = __float_as_uint(v.z);
                afr[mt][3] = __float_as_uint(v.w);
            }
            #pragma unroll
            for (int nt = 0; nt < 4; nt++) {
                int ni = wn * 4 + nt;
                float2 bv = *reinterpret_cast<const float2*>(
                    Bs + ((ni * 4 + kb) * 32 + lane) * 2);
                unsigned b0 = __float_as_uint(bv.x);
                unsigned b1 = __float_as_uint(bv.y);
                mma_tf32(acc[0][nt], afr[0], b0, b1);
                mma_tf32(acc[1][nt], afr[1], b0, b1);
            }
        }
        __syncthreads();
    }

    int g = lane >> 2, tg = lane & 3;
    int m0 = blockIdx.x * 64;
    int n0g = blockIdx.y * 128;
    #pragma unroll
    for (int mt = 0; mt < 2; mt++) {
        int r0 = m0 + wm * 32 + mt * 16 + g;
        #pragma unroll
        for (int nt = 0; nt < 4; nt++) {
            int col = n0g + wn * 32 + nt * 8 + tg * 2;
            float* Cp = C0;
            int c = col;
            if (col >= H) { Cp = C1; c = col - H; }
            if (r0 < M)
                *reinterpret_cast<float2*>(Cp + (size_t)r0 * H + c) =
                    make_float2(acc[mt][nt][0], acc[mt][nt][1]);
            if (r0 + 8 < M)
                *reinterpret_cast<float2*>(Cp + (size_t)(r0 + 8) * H + c) =
                    make_float2(acc[mt][nt][2], acc[mt][nt][3]);
        }
    }
}

// ---------------- GEMM2: cp.async double-buffered (R12-proven path) ----------------
#define AS_STRIDE 36
#define BS_STRIDE 136
#define AS_STAGE  (64 * AS_STRIDE)
#define BS_STAGE  (32 * BS_STRIDE)
#define SMEM_MMA_BYTES ((2 * AS_STAGE + 2 * BS_STAGE) * 4)

__global__ __launch_bounds__(256) void k_mma(
    const float* __restrict__ A,
    const float* __restrict__ B0, const float* __restrict__ B1,
    float* __restrict__ C0, float* __restrict__ C1,
    int M, int K, int H)
{
    extern __shared__ float smem[];
    float* sAs = smem;
    float* sBs = smem + 2 * AS_STAGE;

    int tid = threadIdx.x;
    int lane = tid & 31, warp = tid >> 5;
    int wm = warp & 1, wn = warp >> 1;
    int m0 = blockIdx.x * 64;
    int n0g = blockIdx.y * 128;
    int g = lane >> 2, tg = lane & 3;

    float acc[2][4][4];
    #pragma unroll
    for (int mt = 0; mt < 2; mt++)
        #pragma unroll
        for (int nt = 0; nt < 4; nt++)
            #pragma unroll
            for (int i = 0; i < 4; i++) acc[mt][nt][i] = 0.f;

    int ar = tid >> 2;
    int ac = (tid & 3) * 8;
    int br = tid >> 3;
    int bc = (tid & 7) * 16;

    int arow = m0 + ar;
    int apred = (arow < M) ? 16 : 0;
    if (arow >= M) arow = M - 1;
    const float* abase = A + (size_t)arow * K + ac;

    const float* bsrc[4];
    #pragma unroll
    for (int i = 0; i < 4; i++) {
        int col = n0g + bc + i * 4;
        bsrc[i] = (col < H) ? (B0 + (size_t)br * H + col)
                            : (B1 + (size_t)br * H + (col - H));
    }

    uint32_t sA0 = (uint32_t)__cvta_generic_to_shared(sAs);
    uint32_t sB0 = (uint32_t)__cvta_generic_to_shared(sBs);

    int nIter = K >> 5;

    auto load_stage = [&](int k0, int st) {
        uint32_t sa = sA0 + (st * AS_STAGE + ar * AS_STRIDE + ac) * 4;
        const float* ap = abase + k0;
        cp_async16(sa,      ap,     apred);
        cp_async16(sa + 16, ap + 4, apred);
        uint32_t sb = sB0 + (st * BS_STAGE + br * BS_STRIDE + bc) * 4;
        size_t koff = (size_t)k0 * H;
        #pragma unroll
        for (int i = 0; i < 4; i++)
            cp_async16(sb + i * 16, bsrc[i] + koff, 16);
    };

    load_stage(0, 0);
    asm volatile("cp.async.commit_group;" ::: "memory");

    for (int it = 0; it < nIter; it++) {
        int st = it & 1;
        asm volatile("cp.async.wait_group 0;" ::: "memory");
        __syncthreads();
        if (it + 1 < nIter) {
            load_stage((it + 1) << 5, st ^ 1);
            asm volatile("cp.async.commit_group;" ::: "memory");
        }

        const float* As = sAs + st * AS_STAGE;
        const float* Bs = sBs + st * BS_STAGE;

        #pragma unroll
        for (int kk = 0; kk < 32; kk += 8) {
            unsigned afr[2][4];
            #pragma unroll
            for (int mt = 0; mt < 2; mt++) {
                int row = wm * 32 + mt * 16;
                afr[mt][0] = __float_as_uint(As[(row + g    ) * AS_STRIDE + kk + tg    ]);
                afr[mt][1] = __float_as_uint(As[(row + g + 8) * AS_STRIDE + kk + tg    ]);
                afr[mt][2] = __float_as_uint(As[(row + g    ) * AS_STRIDE + kk + tg + 4]);
                afr[mt][3] = __float_as_uint(As[(row + g + 8) * AS_STRIDE + kk + tg + 4]);
            }
            #pragma unroll
            for (int nt = 0; nt < 4; nt++) {
                int ncol = wn * 32 + nt * 8;
                unsigned b0 = __float_as_uint(Bs[(kk + tg    ) * BS_STRIDE + ncol + g]);
                unsigned b1 = __float_as_uint(Bs[(kk + tg + 4) * BS_STRIDE + ncol + g]);
                #pragma unroll
                for (int mt = 0; mt < 2; mt++)
                    mma_tf32(acc[mt][nt], afr[mt], b0, b1);
            }
        }
        __syncthreads();
    }

    #pragma unroll
    for (int mt = 0; mt < 2; mt++) {
        int r0 = m0 + wm * 32 + mt * 16 + g;
        #pragma unroll
        for (int nt = 0; nt < 4; nt++) {
            int col = n0g + wn * 32 + nt * 8 + tg * 2;
            float* Cp = C0;
            int c = col;
            if (col >= H) { Cp = C1; c = col - H; }
            if (r0 < M)
                *reinterpret_cast<float2*>(Cp + (size_t)r0 * H + c) =
                    make_float2(acc[mt][nt][0], acc[mt][nt][1]);
            if (r0 + 8 < M)
                *reinterpret_cast<float2*>(Cp + (size_t)(r0 + 8) * H + c) =
                    make_float2(acc[mt][nt][2], acc[mt][nt][3]);
        }
    }
}

// ---------------- vector load helper ----------------
template <int V>
__device__ __forceinline__ void loadv(float* d, const float* __restrict__ p) {
    if constexpr (V == 8) {
        float4 a = *reinterpret_cast<const float4*>(p);
        float4 b = *reinterpret_cast<const float4*>(p + 4);
        d[0] = a.x; d[1] = a.y; d[2] = a.z; d[3] = a.w;
        d[4] = b.x; d[5] = b.y; d[6] = b.z; d[7] = b.w;
    } else if constexpr (V == 2) {
        float2 a = *reinterpret_cast<const float2*>(p);
        d[0] = a.x; d[1] = a.y;
    } else {
        #pragma unroll
        for (int j = 0; j < V; j++) d[j] = p[j];
    }
}

// ---------------- GATv2 node aggregation: warp per node, online softmax ----------------
template <int HC, int VPT, int REDW, bool ELU_ACT, bool STATS, bool TF32OUT, bool UN4>
__global__ __launch_bounds__(256) void k_node_agg(
    const float* __restrict__ xl, const float* __restrict__ xr,
    const float* __restrict__ att, const float* __restrict__ bias,
    float* __restrict__ outp, int N)
{
    __shared__ float sh_sum[STATS ? 64 : 1];
    __shared__ float sh_sq [STATS ? 64 : 1];
    int tid = threadIdx.x;
    if (STATS) {
        if (tid < 64) { sh_sum[tid] = 0.f; sh_sq[tid] = 0.f; }
        __syncthreads();
    }

    int warp = (blockIdx.x * blockDim.x + tid) >> 5;
    int lane = tid & 31;
    bool active = warp < N;
    int c0 = lane * VPT;

    if (active) {
        int n = warp;
        float xrv[VPT], attv[VPT], acc[VPT];
        loadv<VPT>(xrv, xr + (size_t)n * HC + c0);
        loadv<VPT>(attv, att + c0);
        #pragma unroll
        for (int j = 0; j < VPT; j++) acc[j] = 0.f;

        float m = __int_as_float(0xff800000);   // -inf
        float denom = 0.f;

        int s = g_off[n], e = g_end[n];
        int i = s;

        if (UN4) {
            for (; i + 4 <= e; i += 4) {
                int s0 = g_csrc[i], s1 = g_csrc[i + 1];
                int s2 = g_csrc[i + 2], s3 = g_csrc[i + 3];
                float x0[VPT], x1[VPT], x2[VPT], x3[VPT];
                loadv<VPT>(x0, xl + (size_t)s0 * HC + c0);
                loadv<VPT>(x1, xl + (size_t)s1 * HC + c0);
                loadv<VPT>(x2, xl + (size_t)s2 * HC + c0);
                loadv<VPT>(x3, xl + (size_t)s3 * HC + c0);

                float sc0 = 0.f, sc1 = 0.f, sc2 = 0.f, sc3 = 0.f;
                #pragma unroll
                for (int j = 0; j < VPT; j++) {
                    float t0 = x0[j] + xrv[j], t1 = x1[j] + xrv[j];
                    float t2 = x2[j] + xrv[j], t3 = x3[j] + xrv[j];
                    t0 = (t0 > 0.f) ? t0 : 0.2f * t0;
                    t1 = (t1 > 0.f) ? t1 : 0.2f * t1;
                    t2 = (t2 > 0.f) ? t2 : 0.2f * t2;
                    t3 = (t3 > 0.f) ? t3 : 0.2f * t3;
                    sc0 = fmaf(t0, attv[j], sc0);
                    sc1 = fmaf(t1, attv[j], sc1);
                    sc2 = fmaf(t2, attv[j], sc2);
                    sc3 = fmaf(t3, attv[j], sc3);
                }
                #pragma unroll
                for (int w = 1; w < REDW; w <<= 1) {
                    sc0 += __shfl_xor_sync(0xffffffffu, sc0, w);
                    sc1 += __shfl_xor_sync(0xffffffffu, sc1, w);
                    sc2 += __shfl_xor_sync(0xffffffffu, sc2, w);
                    sc3 += __shfl_xor_sync(0xffffffffu, sc3, w);
                }
                float newm = fmaxf(fmaxf(m, fmaxf(sc0, sc1)), fmaxf(sc2, sc3));
                float r  = __expf(m - newm);
                float e0 = __expf(sc0 - newm);
                float e1 = __expf(sc1 - newm);
                float e2 = __expf(sc2 - newm);
                float e3 = __expf(sc3 - newm);
                denom = fmaf(denom, r, (e0 + e1) + (e2 + e3));
                #pragma unroll
                for (int j = 0; j < VPT; j++) {
                    float t = fmaf(e0, x0[j], e1 * x1[j]);
                    t = fmaf(e2, x2[j], t);
                    t = fmaf(e3, x3[j], t);
                    acc[j] = fmaf(acc[j], r, t);
                }
                m = newm;
            }
        }

        for (; i + 2 <= e; i += 2) {
            int s0 = g_csrc[i];
            int s1 = g_csrc[i + 1];
            float xlv0[VPT], xlv1[VPT];
            loadv<VPT>(xlv0, xl + (size_t)s0 * HC + c0);
            loadv<VPT>(xlv1, xl + (size_t)s1 * HC + c0);

            float sc0 = 0.f, sc1 = 0.f;
            #pragma unroll
            for (int j = 0; j < VPT; j++) {
                float t0 = xlv0[j] + xrv[j];
                float t1 = xlv1[j] + xrv[j];
                t0 = (t0 > 0.f) ? t0 : 0.2f * t0;
                t1 = (t1 > 0.f) ? t1 : 0.2f * t1;
                sc0 = fmaf(t0, attv[j], sc0);
                sc1 = fmaf(t1, attv[j], sc1);
            }
            #pragma unroll
            for (int w = 1; w < REDW; w <<= 1) {
                sc0 += __shfl_xor_sync(0xffffffffu, sc0, w);
                sc1 += __shfl_xor_sync(0xffffffffu, sc1, w);
            }

            float newm = fmaxf(m, fmaxf(sc0, sc1));
            float r  = __expf(m - newm);       // 0 on first iter (m = -inf)
            float e0 = __expf(sc0 - newm);
            float e1 = __expf(sc1 - newm);
            denom = fmaf(denom, r, e0 + e1);
            #pragma unroll
            for (int j = 0; j < VPT; j++)
                acc[j] = fmaf(acc[j], r, fmaf(e0, xlv0[j], e1 * xlv1[j]));
            m = newm;
        }
        if (i < e) {
            int src = g_csrc[i];
            float xlv[VPT];
            loadv<VPT>(xlv, xl + (size_t)src * HC + c0);
            float sc = 0.f;
            #pragma unroll
            for (int j = 0; j < VPT; j++) {
                float t = xlv[j] + xrv[j];
                t = (t > 0.f) ? t : 0.2f * t;
                sc = fmaf(t, attv[j], sc);
            }
            #pragma unroll
            for (int w = 1; w < REDW; w <<= 1)
                sc += __shfl_xor_sync(0xffffffffu, sc, w);
            if (sc > m) {
                float r = __expf(m - sc);
                denom *= r;
                #pragma unroll
                for (int j = 0; j < VPT; j++) acc[j] *= r;
                m = sc;
            }
            float ex = __expf(sc - m);
            denom += ex;
            #pragma unroll
            for (int j = 0; j < VPT; j++) acc[j] = fmaf(ex, xlv[j], acc[j]);
        }

        float inv = 1.f / (denom + 1e-16f);
        #pragma unroll
        for (int j = 0; j < VPT; j++) {
            float v = acc[j] * inv + bias[c0 + j];
            if (ELU_ACT) v = (v > 0.f) ? v : (__expf(v) - 1.f);  // ELU alpha=1
            float w = TF32OUT ? tfv(v) : v;
            outp[(size_t)n * HC + c0 + j] = w;
            if (STATS) {
                atomicAdd(&sh_sum[c0 + j], v);
                atomicAdd(&sh_sq [c0 + j], v * v);
            }
        }
    }

    if (STATS) {
        __syncthreads();
        if (tid < 64) {
            atomicAdd(&g_sum[tid],   sh_sum[tid]);
            atomicAdd(&g_sumsq[tid], sh_sq[tid]);
        }
    }
}

// ---------------- InstanceNorm + log_softmax epilogue (warp per node) ----------------
__global__ __launch_bounds__(256) void k_final(
    const float* __restrict__ h,
    const float* __restrict__ gamma, const float* __restrict__ beta,
    float* __restrict__ out, int N)
{
    int gw = (blockIdx.x * blockDim.x + threadIdx.x) >> 5;
    int lane = threadIdx.x & 31;
    if (gw >= N) return;
    int c0 = lane * 2;

    float2 x = *reinterpret_cast<const float2*>(h + (size_t)gw * 64 + c0);
    float invN = 1.f / (float)N;

    float mean0 = g_sum[c0] * invN;
    float var0  = g_sumsq[c0] * invN - mean0 * mean0;
    float y0 = (x.x - mean0) * rsqrtf(var0 + 1e-5f) * gamma[c0] + beta[c0];

    float mean1 = g_sum[c0 + 1] * invN;
    float var1  = g_sumsq[c0 + 1] * invN - mean1 * mean1;
    float y1 = (x.y - mean1) * rsqrtf(var1 + 1e-5f) * gamma[c0 + 1] + beta[c0 + 1];

    float2 yv = make_float2(y0, y1);
    *reinterpret_cast<float2*>(out + (size_t)gw * 64 + c0) = yv;

    float mx = fmaxf(y0, y1);
    #pragma unroll
    for (int w = 1; w < 32; w <<= 1) mx = fmaxf(mx, __shfl_xor_sync(0xffffffffu, mx, w));
    float se = __expf(y0 - mx) + __expf(y1 - mx);
    #pragma unroll
    for (int w = 1; w < 32; w <<= 1) se += __shfl_xor_sync(0xffffffffu, se, w);
    float ls = __logf(se) + mx;          // log-sum-exp

    float2 lv = make_float2(y0 - ls, y1 - ls);
    *reinterpret_cast<float2*>(out + (size_t)N * 64 + (size_t)gw * 64 + c0) = lv;
}

// ---------------- host launcher ----------------
extern "C" void kernel_launch(void* const* d_in, const int* in_sizes, int n_in,
                              void* d_out, int out_size)
{
    const float* x     = (const float*)d_in[0];
    const float* Wl1   = (const float*)d_in[1];
    const float* Wr1   = (const float*)d_in[2];
    const float* att1  = (const float*)d_in[3];
    const float* b1    = (const float*)d_in[4];
    const float* Wl2   = (const float*)d_in[5];
    const float* Wr2   = (const float*)d_in[6];
    const float* att2  = (const float*)d_in[7];
    const float* b2    = (const float*)d_in[8];
    const float* gamma = (const float*)d_in[9];
    const float* beta  = (const float*)d_in[10];
    const int*   ei    = (const int*)  d_in[11];   // [2, E] int32

    int N = in_sizes[0] / 128;
    int E = in_sizes[11] / 2;

    void *p;
    cudaGetSymbolAddress(&p, g_xl1); float* xl1 = (float*)p;
    cudaGetSymbolAddress(&p, g_xr1); float* xr1 = (float*)p;
    cudaGetSymbolAddress(&p, g_h1 ); float* h1  = (float*)p;
    cudaGetSymbolAddress(&p, g_xl2); float* xl2 = (float*)p;
    cudaGetSymbolAddress(&p, g_xr2); float* xr2 = (float*)p;
    cudaGetSymbolAddress(&p, g_h2 ); float* h2  = (float*)p;
    cudaGetSymbolAddress(&p, g_xp  ); float* xp   = (float*)p;
    cudaGetSymbolAddress(&p, g_w1p ); float* w1p  = (float*)p;
    cudaGetSymbolAddress(&p, g_wl2c); float* wl2c = (float*)p;
    cudaGetSymbolAddress(&p, g_wr2c); float* wr2c = (float*)p;

    static cudaStream_t s2 = nullptr;
    static cudaEvent_t evFork = nullptr, evJoin = nullptr;
    static bool init_done = false;
    if (!init_done) {
        cudaFuncSetAttribute(k_mma, cudaFuncAttributeMaxDynamicSharedMemorySize,
                             SMEM_MMA_BYTES);
        cudaFuncSetAttribute(k_mma_p1, cudaFuncAttributeMaxDynamicSharedMemorySize,
                             SMEM_P1);
        cudaStreamCreateWithFlags(&s2, cudaStreamNonBlocking);
        cudaEventCreateWithFlags(&evFork, cudaEventDisableTiming);
        cudaEventCreateWithFlags(&evJoin, cudaEventDisableTiming);
        init_done = true;
    }

    int e4 = (E + 3) / 4;
    int mtiles = (N + 63) / 64;

    // ---- fork: CSR build on s2, prep + GEMM1 on the main stream ----
    cudaEventRecord(evFork, 0);
    cudaStreamWaitEvent(s2, evFork, 0);

    k_initdeg<<<(N + 255) / 256, 256, 0, s2>>>(N);
    k_count<<<(e4 + 255) / 256, 256, 0, s2>>>(ei, E);
    k_offsets<<<(N + 255) / 256, 256, 0, s2>>>(N);
    k_fill<<<(e4 + 255) / 256, 256, 0, s2>>>(ei, E);
    cudaEventRecord(evJoin, s2);

    k_prep<<<1024, 256>>>(x, Wl1, Wr1, Wl2, Wr2, N);
    {
        dim3 grid(mtiles, 4);
        k_mma_p1<<<grid, 256, SMEM_P1>>>(xp, w1p, xl1, xr1, N);
    }

    // ---- join ----
    cudaStreamWaitEvent(0, evJoin, 0);

    // GATv2 layer 1 (H=8, C=32) + bias + ELU, output tf32-rounded for GEMM2
    k_node_agg<256, 8, 4, true, false, true, false><<<(N * 32 + 255) / 256, 256>>>(
        xl1, xr1, att1, b1, h1, N);

    // Layer 2: [xl2 | xr2] = h1 @ [wl2c | wr2c]  (M=N, K=256, H=64, 2H=128)
    {
        dim3 grid((N + 63) / 64, 1);
        k_mma<<<grid, 256, SMEM_MMA_BYTES>>>(h1, wl2c, wr2c, xl2, xr2, N, 256, 64);
    }
    // GATv2 layer 2 (H=1, C=64) + bias + fused InstanceNorm stats, 4-edge unroll
    k_node_agg<64, 2, 32, false, true, false, true><<<(N * 32 + 255) / 256, 256>>>(
        xl2, xr2, att2, b2, h2, N);

    // InstanceNorm normalize + log_softmax
    k_final<<<(N * 32 + 255) / 256, 256>>>(h2, gamma, beta, (float*)d_out, N);
}